// round 1
// baseline (speedup 1.0000x reference)
#include <cuda_runtime.h>

#define NDIM 512
#define DDIM 128
#define NN (NDIM*NDIM)
#define R1 64
#define PSTR 132
#define WSTR 132
#define THREADS 256

// Scratch (device globals; no allocations allowed)
__device__ float g_left[(size_t)NN*DDIM];
__device__ float g_right[(size_t)NN*DDIM];
__device__ float g_gate[(size_t)NN*DDIM];
__device__ float g_acc[(size_t)NN*DDIM];

__device__ __forceinline__ float sigf(float x){ return 1.0f/(1.0f+__expf(-x)); }

// cooperative weight load [128][128] -> padded smem
__device__ __forceinline__ void load_w(const float* __restrict__ W, float* ws, int tid){
    for (int idx = tid; idx < DDIM*DDIM/4; idx += THREADS){
        int d = idx >> 5;
        int e = (idx & 31) << 2;
        *(float4*)&ws[d*WSTR + e] = *(const float4*)&W[idx << 2];
    }
}

// 64x128 tile GEMM against two 128x128 weights (out[r][d] = sum_e p[r][e]*W[d][e])
// thread (tx,ty): rows ty*4..+3, cols d = tx + 16*j (j=0..7)
__device__ __forceinline__ void gemm_pair(const float* __restrict__ p_s,
                                          const float* __restrict__ wa,
                                          const float* __restrict__ wb,
                                          float (&accp)[4][8], float (&accg)[4][8],
                                          int tx, int ty){
    const float* pp = p_s + ty*4*PSTR;
    #pragma unroll 1
    for (int e = 0; e < DDIM; e += 4){
        float4 pv[4];
        #pragma unroll
        for (int i = 0; i < 4; i++) pv[i] = *(const float4*)&pp[i*PSTR + e];
        #pragma unroll
        for (int j = 0; j < 8; j++){
            float4 w = *(const float4*)&wa[(tx + 16*j)*WSTR + e];
            #pragma unroll
            for (int i = 0; i < 4; i++){
                accp[i][j] = fmaf(pv[i].x, w.x, accp[i][j]);
                accp[i][j] = fmaf(pv[i].y, w.y, accp[i][j]);
                accp[i][j] = fmaf(pv[i].z, w.z, accp[i][j]);
                accp[i][j] = fmaf(pv[i].w, w.w, accp[i][j]);
            }
            float4 g = *(const float4*)&wb[(tx + 16*j)*WSTR + e];
            #pragma unroll
            for (int i = 0; i < 4; i++){
                accg[i][j] = fmaf(pv[i].x, g.x, accg[i][j]);
                accg[i][j] = fmaf(pv[i].y, g.y, accg[i][j]);
                accg[i][j] = fmaf(pv[i].z, g.z, accg[i][j]);
                accg[i][j] = fmaf(pv[i].w, g.w, accg[i][j]);
            }
        }
    }
}

__device__ __forceinline__ void gemm_one(const float* __restrict__ p_s,
                                         const float* __restrict__ wa,
                                         float (&acc)[4][8], int tx, int ty){
    const float* pp = p_s + ty*4*PSTR;
    #pragma unroll 1
    for (int e = 0; e < DDIM; e += 4){
        float4 pv[4];
        #pragma unroll
        for (int i = 0; i < 4; i++) pv[i] = *(const float4*)&pp[i*PSTR + e];
        #pragma unroll
        for (int j = 0; j < 8; j++){
            float4 w = *(const float4*)&wa[(tx + 16*j)*WSTR + e];
            #pragma unroll
            for (int i = 0; i < 4; i++){
                acc[i][j] = fmaf(pv[i].x, w.x, acc[i][j]);
                acc[i][j] = fmaf(pv[i].y, w.y, acc[i][j]);
                acc[i][j] = fmaf(pv[i].z, w.z, acc[i][j]);
                acc[i][j] = fmaf(pv[i].w, w.w, acc[i][j]);
            }
        }
    }
}

// ---------------- Kernel 1: LN + 5 gated projections ----------------
__global__ void __launch_bounds__(THREADS)
k1_ln_proj(const float* __restrict__ pair, const float* __restrict__ mask,
           const float* __restrict__ nw,  const float* __restrict__ nb,
           const float* __restrict__ lpw, const float* __restrict__ lpb,
           const float* __restrict__ lgw, const float* __restrict__ lgb,
           const float* __restrict__ rpw, const float* __restrict__ rpb,
           const float* __restrict__ rgw, const float* __restrict__ rgb,
           const float* __restrict__ ogw, const float* __restrict__ ogb)
{
    extern __shared__ float sm[];
    float* p_s = sm;                       // R1*PSTR
    float* wa  = sm + R1*PSTR;             // DDIM*WSTR
    float* wb  = wa + DDIM*WSTR;           // DDIM*WSTR
    __shared__ float sred[4][64];
    __shared__ float qred[4][64];
    __shared__ float mean_s[64], inv_s[64];

    const int tid  = threadIdx.x;
    const int row0 = blockIdx.x * R1;

    // ---- load pair rows into smem ----
    for (int idx = tid; idx < R1*DDIM/4; idx += THREADS){
        int r = idx >> 5;
        int e = (idx & 31) << 2;
        *(float4*)&p_s[r*PSTR + e] = *(const float4*)&pair[(size_t)row0*DDIM + (idx << 2)];
    }
    __syncthreads();

    // ---- LN stats (4 threads per row) ----
    {
        int r = tid & 63, q = tid >> 6;
        float s = 0.f, ss = 0.f;
        #pragma unroll
        for (int t = 0; t < 8; t++){
            float4 v = *(const float4*)&p_s[r*PSTR + q*32 + t*4];
            s  += v.x + v.y + v.z + v.w;
            ss += v.x*v.x + v.y*v.y + v.z*v.z + v.w*v.w;
        }
        sred[q][r] = s; qred[q][r] = ss;
    }
    __syncthreads();
    if (tid < 64){
        int r = tid;
        float S  = sred[0][r] + sred[1][r] + sred[2][r] + sred[3][r];
        float SS = qred[0][r] + qred[1][r] + qred[2][r] + qred[3][r];
        float m  = S * (1.f/DDIM);
        float v  = fmaxf(SS * (1.f/DDIM) - m*m, 0.f);
        mean_s[r] = m;
        inv_s[r]  = rsqrtf(v + 1e-5f);
    }
    __syncthreads();
    // ---- normalize in place ----
    for (int idx = tid; idx < R1*DDIM/4; idx += THREADS){
        int r = idx >> 5;
        int e = (idx & 31) << 2;
        float4 v  = *(float4*)&p_s[r*PSTR + e];
        float4 w4 = *(const float4*)&nw[e];
        float4 b4 = *(const float4*)&nb[e];
        float m = mean_s[r], iv = inv_s[r];
        v.x = (v.x - m)*iv*w4.x + b4.x;
        v.y = (v.y - m)*iv*w4.y + b4.y;
        v.z = (v.z - m)*iv*w4.z + b4.z;
        v.w = (v.w - m)*iv*w4.w + b4.w;
        *(float4*)&p_s[r*PSTR + e] = v;
    }

    const int tx = tid & 15, ty = tid >> 4;

    // ---- PASS A: left = (p@lpw.T+lpb)*sigmoid(p@lgw.T+lgb)*mask ----
    __syncthreads();
    load_w(lpw, wa, tid);
    load_w(lgw, wb, tid);
    __syncthreads();
    {
        float accp[4][8], accg[4][8];
        #pragma unroll
        for (int i = 0; i < 4; i++)
            #pragma unroll
            for (int j = 0; j < 8; j++){ accp[i][j] = 0.f; accg[i][j] = 0.f; }
        gemm_pair(p_s, wa, wb, accp, accg, tx, ty);
        #pragma unroll
        for (int i = 0; i < 4; i++){
            int rr = row0 + ty*4 + i;
            float mv = mask[rr];
            #pragma unroll
            for (int j = 0; j < 8; j++){
                int d = tx + 16*j;
                float x = accp[i][j] + lpb[d];
                float g = accg[i][j] + lgb[d];
                g_left[(size_t)rr*DDIM + d] = x * sigf(g) * mv;
            }
        }
    }

    // ---- PASS B: right ----
    __syncthreads();
    load_w(rpw, wa, tid);
    load_w(rgw, wb, tid);
    __syncthreads();
    {
        float accp[4][8], accg[4][8];
        #pragma unroll
        for (int i = 0; i < 4; i++)
            #pragma unroll
            for (int j = 0; j < 8; j++){ accp[i][j] = 0.f; accg[i][j] = 0.f; }
        gemm_pair(p_s, wa, wb, accp, accg, tx, ty);
        #pragma unroll
        for (int i = 0; i < 4; i++){
            int rr = row0 + ty*4 + i;
            float mv = mask[rr];
            #pragma unroll
            for (int j = 0; j < 8; j++){
                int d = tx + 16*j;
                float x = accp[i][j] + rpb[d];
                float g = accg[i][j] + rgb[d];
                g_right[(size_t)rr*DDIM + d] = x * sigf(g) * mv;
            }
        }
    }

    // ---- PASS C: output gate = sigmoid(p@ogw.T + ogb) ----
    __syncthreads();
    load_w(ogw, wa, tid);
    __syncthreads();
    {
        float acc[4][8];
        #pragma unroll
        for (int i = 0; i < 4; i++)
            #pragma unroll
            for (int j = 0; j < 8; j++) acc[i][j] = 0.f;
        gemm_one(p_s, wa, acc, tx, ty);
        #pragma unroll
        for (int i = 0; i < 4; i++){
            int rr = row0 + ty*4 + i;
            #pragma unroll
            for (int j = 0; j < 8; j++){
                int d = tx + 16*j;
                g_gate[(size_t)rr*DDIM + d] = sigf(acc[i][j] + ogb[d]);
            }
        }
    }
}

// ---------------- Kernel 2: per-channel einsum bikd,bjkd->bijd ----------------
// block: 32 i x 32 j x 16 d, K loop chunked by 8.
#define KC 8
__global__ void __launch_bounds__(THREADS)
k2_einsum()
{
    __shared__ float ls[KC][32][16];
    __shared__ float rs[KC][32][16];

    const int tid = threadIdx.x;
    const int dt = tid & 15;
    const int jt = (tid >> 4) & 3;
    const int it = tid >> 6;

    const int j0 = blockIdx.x * 32;
    const int i0 = blockIdx.y * 32;
    const int d0 = blockIdx.z * 16;

    float acc[8][8];
    #pragma unroll
    for (int a = 0; a < 8; a++)
        #pragma unroll
        for (int b = 0; b < 8; b++) acc[a][b] = 0.f;

    for (int kc = 0; kc < NDIM; kc += KC){
        __syncthreads();
        #pragma unroll
        for (int t = 0; t < 4; t++){
            int idx = tid + t*THREADS;          // 0..1023
            int dd = (idx & 3) << 2;            // 0,4,8,12
            int k  = (idx >> 2) & (KC-1);
            int i  = idx >> 5;                  // 0..31
            int gl = ((i0 + i)*NDIM + kc + k)*DDIM + d0 + dd;
            int gr = ((j0 + i)*NDIM + kc + k)*DDIM + d0 + dd;
            *(float4*)&ls[k][i][dd] = *(const float4*)&g_left[gl];
            *(float4*)&rs[k][i][dd] = *(const float4*)&g_right[gr];
        }
        __syncthreads();
        #pragma unroll
        for (int k = 0; k < KC; k++){
            float lv[8], rv[8];
            #pragma unroll
            for (int a = 0; a < 8; a++) lv[a] = ls[k][it*8 + a][dt];
            #pragma unroll
            for (int b = 0; b < 8; b++) rv[b] = rs[k][jt*8 + b][dt];
            #pragma unroll
            for (int a = 0; a < 8; a++)
                #pragma unroll
                for (int b = 0; b < 8; b++)
                    acc[a][b] = fmaf(lv[a], rv[b], acc[a][b]);
        }
    }

    #pragma unroll
    for (int a = 0; a < 8; a++){
        int gi = i0 + it*8 + a;
        #pragma unroll
        for (int b = 0; b < 8; b++){
            int gj = j0 + jt*8 + b;
            g_acc[(size_t)(gi*NDIM + gj)*DDIM + d0 + dt] = acc[a][b];
        }
    }
}

// ---------------- Kernel 3: LN(acc) @ opw.T + opb, times gate ----------------
__global__ void __launch_bounds__(THREADS)
k3_out(const float* __restrict__ onw, const float* __restrict__ onb,
       const float* __restrict__ opw, const float* __restrict__ opb,
       float* __restrict__ out)
{
    extern __shared__ float sm[];
    float* p_s = sm;
    float* wa  = sm + R1*PSTR;
    __shared__ float sred[4][64];
    __shared__ float qred[4][64];
    __shared__ float mean_s[64], inv_s[64];

    const int tid  = threadIdx.x;
    const int row0 = blockIdx.x * R1;

    for (int idx = tid; idx < R1*DDIM/4; idx += THREADS){
        int r = idx >> 5;
        int e = (idx & 31) << 2;
        *(float4*)&p_s[r*PSTR + e] = *(const float4*)&g_acc[(size_t)row0*DDIM + (idx << 2)];
    }
    __syncthreads();
    {
        int r = tid & 63, q = tid >> 6;
        float s = 0.f, ss = 0.f;
        #pragma unroll
        for (int t = 0; t < 8; t++){
            float4 v = *(const float4*)&p_s[r*PSTR + q*32 + t*4];
            s  += v.x + v.y + v.z + v.w;
            ss += v.x*v.x + v.y*v.y + v.z*v.z + v.w*v.w;
        }
        sred[q][r] = s; qred[q][r] = ss;
    }
    __syncthreads();
    if (tid < 64){
        int r = tid;
        float S  = sred[0][r] + sred[1][r] + sred[2][r] + sred[3][r];
        float SS = qred[0][r] + qred[1][r] + qred[2][r] + qred[3][r];
        float m  = S * (1.f/DDIM);
        float v  = fmaxf(SS * (1.f/DDIM) - m*m, 0.f);
        mean_s[r] = m;
        inv_s[r]  = rsqrtf(v + 1e-5f);
    }
    __syncthreads();
    for (int idx = tid; idx < R1*DDIM/4; idx += THREADS){
        int r = idx >> 5;
        int e = (idx & 31) << 2;
        float4 v  = *(float4*)&p_s[r*PSTR + e];
        float4 w4 = *(const float4*)&onw[e];
        float4 b4 = *(const float4*)&onb[e];
        float m = mean_s[r], iv = inv_s[r];
        v.x = (v.x - m)*iv*w4.x + b4.x;
        v.y = (v.y - m)*iv*w4.y + b4.y;
        v.z = (v.z - m)*iv*w4.z + b4.z;
        v.w = (v.w - m)*iv*w4.w + b4.w;
        *(float4*)&p_s[r*PSTR + e] = v;
    }
    __syncthreads();
    load_w(opw, wa, tid);
    __syncthreads();

    const int tx = tid & 15, ty = tid >> 4;
    float acc[4][8];
    #pragma unroll
    for (int i = 0; i < 4; i++)
        #pragma unroll
        for (int j = 0; j < 8; j++) acc[i][j] = 0.f;
    gemm_one(p_s, wa, acc, tx, ty);

    #pragma unroll
    for (int i = 0; i < 4; i++){
        int rr = row0 + ty*4 + i;
        #pragma unroll
        for (int j = 0; j < 8; j++){
            int d = tx + 16*j;
            float x = acc[i][j] + opb[d];
            out[(size_t)rr*DDIM + d] = x * g_gate[(size_t)rr*DDIM + d];
        }
    }
}

extern "C" void kernel_launch(void* const* d_in, const int* in_sizes, int n_in,
                              void* d_out, int out_size)
{
    const float* pair = (const float*)d_in[0];
    const float* mask = (const float*)d_in[1];
    const float* nw   = (const float*)d_in[2];
    const float* nb   = (const float*)d_in[3];
    const float* lpw  = (const float*)d_in[4];
    const float* lpb  = (const float*)d_in[5];
    const float* lgw  = (const float*)d_in[6];
    const float* lgb  = (const float*)d_in[7];
    const float* rpw  = (const float*)d_in[8];
    const float* rpb  = (const float*)d_in[9];
    const float* rgw  = (const float*)d_in[10];
    const float* rgb  = (const float*)d_in[11];
    const float* onw  = (const float*)d_in[12];
    const float* onb  = (const float*)d_in[13];
    const float* opw  = (const float*)d_in[14];
    const float* opb  = (const float*)d_in[15];
    const float* ogw  = (const float*)d_in[16];
    const float* ogb  = (const float*)d_in[17];
    float* out = (float*)d_out;

    const int smem1 = (R1*PSTR + 2*DDIM*WSTR) * (int)sizeof(float);   // ~169 KB
    const int smem3 = (R1*PSTR + 1*DDIM*WSTR) * (int)sizeof(float);   // ~101 KB
    cudaFuncSetAttribute(k1_ln_proj, cudaFuncAttributeMaxDynamicSharedMemorySize, smem1);
    cudaFuncSetAttribute(k3_out,     cudaFuncAttributeMaxDynamicSharedMemorySize, smem3);

    k1_ln_proj<<<NN/R1, THREADS, smem1>>>(pair, mask, nw, nb,
                                          lpw, lpb, lgw, lgb,
                                          rpw, rpb, rgw, rgb,
                                          ogw, ogb);

    dim3 g2(NDIM/32, NDIM/32, DDIM/16);   // (16,16,8) — x = j so consecutive blocks reuse the left tile in L2
    k2_einsum<<<g2, THREADS>>>();

    k3_out<<<NN/R1, THREADS, smem3>>>(onw, onb, opw, opb, out);
}

// round 4
// speedup vs baseline: 1.4224x; 1.4224x over previous
#include <cuda_runtime.h>
#include <cuda_bf16.h>
#include <cstdint>

#define NDIM 512
#define DDIM 128
#define NN (NDIM*NDIM)
#define R1 64
#define PSTR 132
#define WSTR 132
#define THREADS 256

// ---------------- scratch (device globals; no allocation allowed) ----------------
__device__ __align__(256) __nv_bfloat16 g_lT_hi[(size_t)DDIM*NDIM*NDIM];
__device__ __align__(256) __nv_bfloat16 g_lT_lo[(size_t)DDIM*NDIM*NDIM];
__device__ __align__(256) __nv_bfloat16 g_rT_hi[(size_t)DDIM*NDIM*NDIM];
__device__ __align__(256) __nv_bfloat16 g_rT_lo[(size_t)DDIM*NDIM*NDIM];
__device__ __align__(256) float g_gate[(size_t)NN*DDIM];
__device__ __align__(256) float g_accT[(size_t)DDIM*NDIM*NDIM];   // [d][i][j]

__device__ __forceinline__ float sigf(float x){ return 1.0f/(1.0f+__expf(-x)); }

__device__ __forceinline__ uint32_t split_pack(float v){
    __nv_bfloat16 h = __float2bfloat16(v);
    float hf = __bfloat162float(h);
    __nv_bfloat16 l = __float2bfloat16(v - hf);
    return (uint32_t)__bfloat16_as_ushort(h) | ((uint32_t)__bfloat16_as_ushort(l) << 16);
}

__device__ __forceinline__ uint32_t smem_u32(const void* p){
    uint32_t a;
    asm("{ .reg .u64 t; cvta.to.shared.u64 t, %1; cvt.u32.u64 %0, t; }" : "=r"(a) : "l"(p));
    return a;
}

// ---------------- baseline-PTX tensor-core helpers (sm_80-era, valid on sm_103) ----------------
__device__ __forceinline__ void ldsm4(uint32_t (&r)[4], uint32_t a){
    asm volatile("ldmatrix.sync.aligned.m8n8.x4.shared.b16 {%0,%1,%2,%3}, [%4];"
        : "=r"(r[0]), "=r"(r[1]), "=r"(r[2]), "=r"(r[3]) : "r"(a));
}
// non-trans x2: for K-major B (rows = n, 16B of contiguous k) -> col-major B fragment
__device__ __forceinline__ void ldsm2(uint32_t (&r)[2], uint32_t a){
    asm volatile("ldmatrix.sync.aligned.m8n8.x2.shared.b16 {%0,%1}, [%2];"
        : "=r"(r[0]), "=r"(r[1]) : "r"(a));
}
__device__ __forceinline__ void mma_bf16(float (&c)[4], const uint32_t (&a)[4], const uint32_t (&b)[2]){
    asm volatile("mma.sync.aligned.m16n8k16.row.col.f32.bf16.bf16.f32 "
        "{%0,%1,%2,%3}, {%4,%5,%6,%7}, {%8,%9}, {%0,%1,%2,%3};"
        : "+f"(c[0]), "+f"(c[1]), "+f"(c[2]), "+f"(c[3])
        : "r"(a[0]), "r"(a[1]), "r"(a[2]), "r"(a[3]), "r"(b[0]), "r"(b[1]));
}
#define CP_ASYNC16(dst, src) \
    asm volatile("cp.async.cg.shared.global [%0], [%1], 16;" :: "r"(dst), "l"(src) : "memory")
#define CP_COMMIT() asm volatile("cp.async.commit_group;" ::: "memory")

// ---------------- shared k1/k3 building blocks (fp32 CUDA-core GEMM) ----------------
__device__ __forceinline__ void load_w(const float* __restrict__ W, float* ws, int tid){
    for (int idx = tid; idx < DDIM*DDIM/4; idx += THREADS){
        int d = idx >> 5;
        int e = (idx & 31) << 2;
        *(float4*)&ws[d*WSTR + e] = *(const float4*)&W[idx << 2];
    }
}

__device__ __forceinline__ void gemm_pair(const float* __restrict__ p_s,
                                          const float* __restrict__ wa,
                                          const float* __restrict__ wb,
                                          float (&accp)[4][8], float (&accg)[4][8],
                                          int tx, int ty){
    const float* pp = p_s + ty*4*PSTR;
    #pragma unroll 1
    for (int e = 0; e < DDIM; e += 4){
        float4 pv[4];
        #pragma unroll
        for (int i = 0; i < 4; i++) pv[i] = *(const float4*)&pp[i*PSTR + e];
        #pragma unroll
        for (int j = 0; j < 8; j++){
            float4 w = *(const float4*)&wa[(tx + 16*j)*WSTR + e];
            #pragma unroll
            for (int i = 0; i < 4; i++){
                accp[i][j] = fmaf(pv[i].x, w.x, accp[i][j]);
                accp[i][j] = fmaf(pv[i].y, w.y, accp[i][j]);
                accp[i][j] = fmaf(pv[i].z, w.z, accp[i][j]);
                accp[i][j] = fmaf(pv[i].w, w.w, accp[i][j]);
            }
            float4 g = *(const float4*)&wb[(tx + 16*j)*WSTR + e];
            #pragma unroll
            for (int i = 0; i < 4; i++){
                accg[i][j] = fmaf(pv[i].x, g.x, accg[i][j]);
                accg[i][j] = fmaf(pv[i].y, g.y, accg[i][j]);
                accg[i][j] = fmaf(pv[i].z, g.z, accg[i][j]);
                accg[i][j] = fmaf(pv[i].w, g.w, accg[i][j]);
            }
        }
    }
}

__device__ __forceinline__ void gemm_one(const float* __restrict__ p_s,
                                         const float* __restrict__ wa,
                                         float (&acc)[4][8], int tx, int ty){
    const float* pp = p_s + ty*4*PSTR;
    #pragma unroll 1
    for (int e = 0; e < DDIM; e += 4){
        float4 pv[4];
        #pragma unroll
        for (int i = 0; i < 4; i++) pv[i] = *(const float4*)&pp[i*PSTR + e];
        #pragma unroll
        for (int j = 0; j < 8; j++){
            float4 w = *(const float4*)&wa[(tx + 16*j)*WSTR + e];
            #pragma unroll
            for (int i = 0; i < 4; i++){
                acc[i][j] = fmaf(pv[i].x, w.x, acc[i][j]);
                acc[i][j] = fmaf(pv[i].y, w.y, acc[i][j]);
                acc[i][j] = fmaf(pv[i].z, w.z, acc[i][j]);
                acc[i][j] = fmaf(pv[i].w, w.w, acc[i][j]);
            }
        }
    }
}

// write the staged (64 k x 128 d) packed tile to [d][i][k] bf16 hi/lo tensors
__device__ __forceinline__ void write_T(const uint32_t* st, __nv_bfloat16* ghi, __nv_bfloat16* glo,
                                        int i_idx, int k0, int tid){
    int dd = tid >> 1, half = tid & 1;
    uint4 oh[4], ol[4];
    unsigned short* hp = (unsigned short*)oh;
    unsigned short* lp = (unsigned short*)ol;
    #pragma unroll
    for (int kk = 0; kk < 32; kk++){
        uint32_t pk = st[(half*32 + kk)*129 + dd];
        hp[kk] = (unsigned short)(pk & 0xFFFFu);
        lp[kk] = (unsigned short)(pk >> 16);
    }
    size_t gb = ((size_t)dd*NDIM + i_idx)*NDIM + k0 + half*32;
    #pragma unroll
    for (int q = 0; q < 4; q++){
        *(uint4*)&ghi[gb + q*8] = oh[q];
        *(uint4*)&glo[gb + q*8] = ol[q];
    }
}

// ---------------- Kernel 1: LN + 5 gated projections ----------------
__global__ void __launch_bounds__(THREADS)
k1_ln_proj(const float* __restrict__ pair, const float* __restrict__ mask,
           const float* __restrict__ nw,  const float* __restrict__ nb,
           const float* __restrict__ lpw, const float* __restrict__ lpb,
           const float* __restrict__ lgw, const float* __restrict__ lgb,
           const float* __restrict__ rpw, const float* __restrict__ rpb,
           const float* __restrict__ rgw, const float* __restrict__ rgb,
           const float* __restrict__ ogw, const float* __restrict__ ogb)
{
    extern __shared__ float sm[];
    float* p_s = sm;                       // R1*PSTR
    float* wa  = sm + R1*PSTR;             // DDIM*WSTR
    float* wb  = wa + DDIM*WSTR;           // DDIM*WSTR
    __shared__ float sred[4][64];
    __shared__ float qred[4][64];
    __shared__ float mean_s[64], inv_s[64];

    const int tid  = threadIdx.x;
    const int row0 = blockIdx.x * R1;
    const int i_idx = row0 >> 9;          // i (since R1=64 divides 512)
    const int k0    = row0 & 511;         // base k within row i

    for (int idx = tid; idx < R1*DDIM/4; idx += THREADS){
        int r = idx >> 5;
        int e = (idx & 31) << 2;
        *(float4*)&p_s[r*PSTR + e] = *(const float4*)&pair[(size_t)row0*DDIM + (idx << 2)];
    }
    __syncthreads();

    {
        int r = tid & 63, q = tid >> 6;
        float s = 0.f, ss = 0.f;
        #pragma unroll
        for (int t = 0; t < 8; t++){
            float4 v = *(const float4*)&p_s[r*PSTR + q*32 + t*4];
            s  += v.x + v.y + v.z + v.w;
            ss += v.x*v.x + v.y*v.y + v.z*v.z + v.w*v.w;
        }
        sred[q][r] = s; qred[q][r] = ss;
    }
    __syncthreads();
    if (tid < 64){
        int r = tid;
        float S  = sred[0][r] + sred[1][r] + sred[2][r] + sred[3][r];
        float SS = qred[0][r] + qred[1][r] + qred[2][r] + qred[3][r];
        float m  = S * (1.f/DDIM);
        float v  = fmaxf(SS * (1.f/DDIM) - m*m, 0.f);
        mean_s[r] = m;
        inv_s[r]  = rsqrtf(v + 1e-5f);
    }
    __syncthreads();
    for (int idx = tid; idx < R1*DDIM/4; idx += THREADS){
        int r = idx >> 5;
        int e = (idx & 31) << 2;
        float4 v  = *(float4*)&p_s[r*PSTR + e];
        float4 w4 = *(const float4*)&nw[e];
        float4 b4 = *(const float4*)&nb[e];
        float m = mean_s[r], iv = inv_s[r];
        v.x = (v.x - m)*iv*w4.x + b4.x;
        v.y = (v.y - m)*iv*w4.y + b4.y;
        v.z = (v.z - m)*iv*w4.z + b4.z;
        v.w = (v.w - m)*iv*w4.w + b4.w;
        *(float4*)&p_s[r*PSTR + e] = v;
    }

    const int tx = tid & 15, ty = tid >> 4;

    // ---- PASS A: left -> split bf16 hi/lo, transposed [d][i][k] ----
    __syncthreads();
    load_w(lpw, wa, tid);
    load_w(lgw, wb, tid);
    __syncthreads();
    {
        float accp[4][8], accg[4][8];
        #pragma unroll
        for (int i = 0; i < 4; i++)
            #pragma unroll
            for (int j = 0; j < 8; j++){ accp[i][j] = 0.f; accg[i][j] = 0.f; }
        gemm_pair(p_s, wa, wb, accp, accg, tx, ty);
        __syncthreads();
        uint32_t* st = (uint32_t*)wa;
        #pragma unroll
        for (int i = 0; i < 4; i++){
            float mv = mask[row0 + ty*4 + i];
            #pragma unroll
            for (int j = 0; j < 8; j++){
                int d = tx + 16*j;
                float x = accp[i][j] + lpb[d];
                float g = accg[i][j] + lgb[d];
                st[(ty*4 + i)*129 + d] = split_pack(x * sigf(g) * mv);
            }
        }
        __syncthreads();
        write_T(st, g_lT_hi, g_lT_lo, i_idx, k0, tid);
    }

    // ---- PASS B: right ----
    __syncthreads();
    load_w(rpw, wa, tid);
    load_w(rgw, wb, tid);
    __syncthreads();
    {
        float accp[4][8], accg[4][8];
        #pragma unroll
        for (int i = 0; i < 4; i++)
            #pragma unroll
            for (int j = 0; j < 8; j++){ accp[i][j] = 0.f; accg[i][j] = 0.f; }
        gemm_pair(p_s, wa, wb, accp, accg, tx, ty);
        __syncthreads();
        uint32_t* st = (uint32_t*)wa;
        #pragma unroll
        for (int i = 0; i < 4; i++){
            float mv = mask[row0 + ty*4 + i];
            #pragma unroll
            for (int j = 0; j < 8; j++){
                int d = tx + 16*j;
                float x = accp[i][j] + rpb[d];
                float g = accg[i][j] + rgb[d];
                st[(ty*4 + i)*129 + d] = split_pack(x * sigf(g) * mv);
            }
        }
        __syncthreads();
        write_T(st, g_rT_hi, g_rT_lo, i_idx, k0, tid);
    }

    // ---- PASS C: output gate (standard layout) ----
    __syncthreads();
    load_w(ogw, wa, tid);
    __syncthreads();
    {
        float acc[4][8];
        #pragma unroll
        for (int i = 0; i < 4; i++)
            #pragma unroll
            for (int j = 0; j < 8; j++) acc[i][j] = 0.f;
        gemm_one(p_s, wa, acc, tx, ty);
        #pragma unroll
        for (int i = 0; i < 4; i++){
            int rr = row0 + ty*4 + i;
            #pragma unroll
            for (int j = 0; j < 8; j++){
                int d = tx + 16*j;
                g_gate[(size_t)rr*DDIM + d] = sigf(acc[i][j] + ogb[d]);
            }
        }
    }
}

// ---------------- Kernel 2: mma.sync split-bf16 batched einsum ----------------
// CTA = (d, 128x128 ij tile). K=512 in 8 chunks of 64, cp.async double buffered.
// 8 warps in 2(M) x 4(N); warp tile 64x32; 3-product split-bf16 per k16.
#define K2_BUF 65536   // 4 tiles x (128 rows x 128B)

__global__ void __launch_bounds__(256, 1)
k2_mma()
{
    extern __shared__ char smraw[];
    char* smb = (char*)(((uintptr_t)smraw + 127) & ~(uintptr_t)127);
    const uint32_t sb = smem_u32(smb);

    const int tid  = threadIdx.x;
    const int lane = tid & 31;
    const int wid  = tid >> 5;
    const int d    = blockIdx.y;
    const int i0   = (blockIdx.x >> 2) * 128;
    const int j0   = (blockIdx.x & 3) * 128;
    const int wm   = wid & 1;         // 0..1
    const int wn   = wid >> 1;        // 0..3

    auto load_chunk = [&](int kc, int b){
        #pragma unroll
        for (int t = 0; t < 16; t++){
            int idx  = tid + (t << 8);       // 0..4095
            int tile = idx >> 10;            // 0..3 : lhi, llo, rhi, rlo
            int r    = (idx >> 3) & 127;
            int c    = idx & 7;              // 16B chunk within 128B row
            const __nv_bfloat16* src = (tile == 0) ? g_lT_hi :
                                       (tile == 1) ? g_lT_lo :
                                       (tile == 2) ? g_rT_hi : g_rT_lo;
            int rb = ((tile & 2) ? j0 : i0) + r;
            const void* gp = &src[((size_t)d*NDIM + rb)*NDIM + kc + (c << 3)];
            uint32_t dst = sb + (b << 16) + (tile << 14) + (r << 7) + (((c ^ (r & 7)) << 4));
            CP_ASYNC16(dst, gp);
        }
        CP_COMMIT();
    };

    float acc[4][4][4];
    #pragma unroll
    for (int a = 0; a < 4; a++)
        #pragma unroll
        for (int b = 0; b < 4; b++)
            #pragma unroll
            for (int q = 0; q < 4; q++) acc[a][b][q] = 0.f;

    load_chunk(0, 0);
    load_chunk(64, 1);

    #pragma unroll 1
    for (int t = 0; t < 8; t++){
        if (t == 7) asm volatile("cp.async.wait_group 0;" ::: "memory");
        else        asm volatile("cp.async.wait_group 1;" ::: "memory");
        __syncthreads();

        const uint32_t base = sb + ((t & 1) << 16);
        #pragma unroll
        for (int kk = 0; kk < 4; kk++){
            uint32_t ah[4][4], al[4][4], bh[4][2], bl[4][2];
            #pragma unroll
            for (int mt = 0; mt < 4; mt++){
                int m = wm*64 + mt*16 + (lane & 15);
                int c = kk*2 + (lane >> 4);
                uint32_t off = (uint32_t)((m << 7) + (((c ^ (m & 7)) << 4)));
                ldsm4(ah[mt], base + off);
                ldsm4(al[mt], base + 16384 + off);
            }
            #pragma unroll
            for (int nt = 0; nt < 4; nt++){
                int l = lane & 15;
                int n = wn*32 + nt*8 + (l & 7);
                int c = kk*2 + (l >> 3);
                uint32_t off = (uint32_t)((n << 7) + (((c ^ (n & 7)) << 4)));
                ldsm2(bh[nt], base + 32768 + off);
                ldsm2(bl[nt], base + 49152 + off);
            }
            #pragma unroll
            for (int mt = 0; mt < 4; mt++)
                #pragma unroll
                for (int nt = 0; nt < 4; nt++){
                    mma_bf16(acc[mt][nt], ah[mt], bh[nt]);
                    mma_bf16(acc[mt][nt], ah[mt], bl[nt]);
                    mma_bf16(acc[mt][nt], al[mt], bh[nt]);
                }
        }
        __syncthreads();
        if (t + 2 < 8) load_chunk((t + 2)*64, t & 1);
    }

    // epilogue: fragments -> g_accT[d][i][j]
    #pragma unroll
    for (int mt = 0; mt < 4; mt++){
        int r0 = i0 + wm*64 + mt*16 + (lane >> 2);
        #pragma unroll
        for (int nt = 0; nt < 4; nt++){
            int c0 = j0 + wn*32 + nt*8 + (lane & 3)*2;
            float* p0 = &g_accT[((size_t)d*NDIM + r0)*NDIM + c0];
            float* p1 = &g_accT[((size_t)d*NDIM + r0 + 8)*NDIM + c0];
            p0[0] = acc[mt][nt][0]; p0[1] = acc[mt][nt][1];
            p1[0] = acc[mt][nt][2]; p1[1] = acc[mt][nt][3];
        }
    }
}

// ---------------- Kernel 3: LN(accT) @ opw.T + opb, times gate ----------------
__global__ void __launch_bounds__(THREADS)
k3_out(const float* __restrict__ onw, const float* __restrict__ onb,
       const float* __restrict__ opw, const float* __restrict__ opb,
       float* __restrict__ out)
{
    extern __shared__ float sm[];
    float* p_s = sm;
    float* wa  = sm + R1*PSTR;
    __shared__ float sred[4][64];
    __shared__ float qred[4][64];
    __shared__ float mean_s[64], inv_s[64];

    const int tid  = threadIdx.x;
    const int row0 = blockIdx.x * R1;
    const int i_idx = row0 >> 9;
    const int j0    = row0 & 511;

    // load from accT[d][i][j-tile] with smem transpose -> p_s[j][d]
    for (int idx = tid; idx < R1*DDIM/4; idx += THREADS){
        int dd = idx >> 4;           // 0..127
        int j4 = (idx & 15) << 2;    // 0..60
        float4 v = *(const float4*)&g_accT[((size_t)dd*NDIM + i_idx)*NDIM + j0 + j4];
        p_s[(j4+0)*PSTR + dd] = v.x;
        p_s[(j4+1)*PSTR + dd] = v.y;
        p_s[(j4+2)*PSTR + dd] = v.z;
        p_s[(j4+3)*PSTR + dd] = v.w;
    }
    __syncthreads();
    {
        int r = tid & 63, q = tid >> 6;
        float s = 0.f, ss = 0.f;
        #pragma unroll
        for (int t = 0; t < 8; t++){
            float4 v = *(const float4*)&p_s[r*PSTR + q*32 + t*4];
            s  += v.x + v.y + v.z + v.w;
            ss += v.x*v.x + v.y*v.y + v.z*v.z + v.w*v.w;
        }
        sred[q][r] = s; qred[q][r] = ss;
    }
    __syncthreads();
    if (tid < 64){
        int r = tid;
        float S  = sred[0][r] + sred[1][r] + sred[2][r] + sred[3][r];
        float SS = qred[0][r] + qred[1][r] + qred[2][r] + qred[3][r];
        float m  = S * (1.f/DDIM);
        float v  = fmaxf(SS * (1.f/DDIM) - m*m, 0.f);
        mean_s[r] = m;
        inv_s[r]  = rsqrtf(v + 1e-5f);
    }
    __syncthreads();
    for (int idx = tid; idx < R1*DDIM/4; idx += THREADS){
        int r = idx >> 5;
        int e = (idx & 31) << 2;
        float4 v  = *(float4*)&p_s[r*PSTR + e];
        float4 w4 = *(const float4*)&onw[e];
        float4 b4 = *(const float4*)&onb[e];
        float m = mean_s[r], iv = inv_s[r];
        v.x = (v.x - m)*iv*w4.x + b4.x;
        v.y = (v.y - m)*iv*w4.y + b4.y;
        v.z = (v.z - m)*iv*w4.z + b4.z;
        v.w = (v.w - m)*iv*w4.w + b4.w;
        *(float4*)&p_s[r*PSTR + e] = v;
    }
    __syncthreads();
    load_w(opw, wa, tid);
    __syncthreads();

    const int tx = tid & 15, ty = tid >> 4;
    float acc[4][8];
    #pragma unroll
    for (int i = 0; i < 4; i++)
        #pragma unroll
        for (int j = 0; j < 8; j++) acc[i][j] = 0.f;
    gemm_one(p_s, wa, acc, tx, ty);

    #pragma unroll
    for (int i = 0; i < 4; i++){
        int rr = row0 + ty*4 + i;
        #pragma unroll
        for (int j = 0; j < 8; j++){
            int d = tx + 16*j;
            float x = acc[i][j] + opb[d];
            out[(size_t)rr*DDIM + d] = x * g_gate[(size_t)rr*DDIM + d];
        }
    }
}

extern "C" void kernel_launch(void* const* d_in, const int* in_sizes, int n_in,
                              void* d_out, int out_size)
{
    const float* pair = (const float*)d_in[0];
    const float* mask = (const float*)d_in[1];
    const float* nw   = (const float*)d_in[2];
    const float* nb   = (const float*)d_in[3];
    const float* lpw  = (const float*)d_in[4];
    const float* lpb  = (const float*)d_in[5];
    const float* lgw  = (const float*)d_in[6];
    const float* lgb  = (const float*)d_in[7];
    const float* rpw  = (const float*)d_in[8];
    const float* rpb  = (const float*)d_in[9];
    const float* rgw  = (const float*)d_in[10];
    const float* rgb  = (const float*)d_in[11];
    const float* onw  = (const float*)d_in[12];
    const float* onb  = (const float*)d_in[13];
    const float* opw  = (const float*)d_in[14];
    const float* opb  = (const float*)d_in[15];
    const float* ogw  = (const float*)d_in[16];
    const float* ogb  = (const float*)d_in[17];
    float* out = (float*)d_out;

    const int smem1 = (R1*PSTR + 2*DDIM*WSTR) * (int)sizeof(float);
    const int smem2 = 2*K2_BUF + 256;
    const int smem3 = (R1*PSTR + 1*DDIM*WSTR) * (int)sizeof(float);
    cudaFuncSetAttribute(k1_ln_proj, cudaFuncAttributeMaxDynamicSharedMemorySize, smem1);
    cudaFuncSetAttribute(k2_mma,     cudaFuncAttributeMaxDynamicSharedMemorySize, smem2);
    cudaFuncSetAttribute(k3_out,     cudaFuncAttributeMaxDynamicSharedMemorySize, smem3);

    k1_ln_proj<<<NN/R1, THREADS, smem1>>>(pair, mask, nw, nb,
                                          lpw, lpb, lgw, lgb,
                                          rpw, rpb, rgw, rgb,
                                          ogw, ogb);

    dim3 g2(16, 128);   // x = (i,j) tile (same d adjacent -> L2 reuse), y = channel d
    k2_mma<<<g2, 256, smem2>>>();

    k3_out<<<NN/R1, THREADS, smem3>>>(onw, onb, opw, opb, out);
}

// round 5
// speedup vs baseline: 2.2093x; 1.5532x over previous
#include <cuda_runtime.h>
#include <cuda_bf16.h>
#include <cstdint>

#define NDIM 512
#define DDIM 128
#define NN (NDIM*NDIM)
#define R1 64
#define PSTR 132
#define WSTR 132
#define THREADS 256

// ---------------- scratch (device globals; no allocation allowed) ----------------
__device__ __align__(256) __nv_bfloat16 g_lT_hi[(size_t)DDIM*NDIM*NDIM];
__device__ __align__(256) __nv_bfloat16 g_lT_lo[(size_t)DDIM*NDIM*NDIM];
__device__ __align__(256) __nv_bfloat16 g_rT_hi[(size_t)DDIM*NDIM*NDIM];
__device__ __align__(256) __nv_bfloat16 g_rT_lo[(size_t)DDIM*NDIM*NDIM];
__device__ __align__(256) float g_gate[(size_t)NN*DDIM];
__device__ __align__(256) float g_accT[(size_t)DDIM*NDIM*NDIM];   // [d][i][j]
// pre-split weights: 0=lp 1=lg 2=rp 3=rg 4=og
__device__ __align__(256) __nv_bfloat16 g_wh[5*16384];
__device__ __align__(256) __nv_bfloat16 g_wl[5*16384];

__device__ __forceinline__ float sigf(float x){ return 1.0f/(1.0f+__expf(-x)); }

__device__ __forceinline__ uint32_t split_pack(float v){
    __nv_bfloat16 h = __float2bfloat16(v);
    float hf = __bfloat162float(h);
    __nv_bfloat16 l = __float2bfloat16(v - hf);
    return (uint32_t)__bfloat16_as_ushort(h) | ((uint32_t)__bfloat16_as_ushort(l) << 16);
}

__device__ __forceinline__ uint32_t smem_u32(const void* p){
    uint32_t a;
    asm("{ .reg .u64 t; cvta.to.shared.u64 t, %1; cvt.u32.u64 %0, t; }" : "=r"(a) : "l"(p));
    return a;
}

// ---------------- baseline-PTX tensor-core helpers ----------------
__device__ __forceinline__ void ldsm4(uint32_t (&r)[4], uint32_t a){
    asm volatile("ldmatrix.sync.aligned.m8n8.x4.shared.b16 {%0,%1,%2,%3}, [%4];"
        : "=r"(r[0]), "=r"(r[1]), "=r"(r[2]), "=r"(r[3]) : "r"(a));
}
__device__ __forceinline__ void ldsm2(uint32_t (&r)[2], uint32_t a){
    asm volatile("ldmatrix.sync.aligned.m8n8.x2.shared.b16 {%0,%1}, [%2];"
        : "=r"(r[0]), "=r"(r[1]) : "r"(a));
}
__device__ __forceinline__ void mma_bf16(float (&c)[4], const uint32_t (&a)[4], const uint32_t (&b)[2]){
    asm volatile("mma.sync.aligned.m16n8k16.row.col.f32.bf16.bf16.f32 "
        "{%0,%1,%2,%3}, {%4,%5,%6,%7}, {%8,%9}, {%0,%1,%2,%3};"
        : "+f"(c[0]), "+f"(c[1]), "+f"(c[2]), "+f"(c[3])
        : "r"(a[0]), "r"(a[1]), "r"(a[2]), "r"(a[3]), "r"(b[0]), "r"(b[1]));
}
#define CP_ASYNC16(dst, src) \
    asm volatile("cp.async.cg.shared.global [%0], [%1], 16;" :: "r"(dst), "l"(src) : "memory")
#define CP_COMMIT() asm volatile("cp.async.commit_group;" ::: "memory")
#define CP_WAIT0()  asm volatile("cp.async.wait_group 0;" ::: "memory")

// ---------------- k3 fp32 building blocks ----------------
__device__ __forceinline__ void load_w(const float* __restrict__ W, float* ws, int tid){
    for (int idx = tid; idx < DDIM*DDIM/4; idx += THREADS){
        int d = idx >> 5;
        int e = (idx & 31) << 2;
        *(float4*)&ws[d*WSTR + e] = *(const float4*)&W[idx << 2];
    }
}

__device__ __forceinline__ void gemm_one(const float* __restrict__ p_s,
                                         const float* __restrict__ wa,
                                         float (&acc)[4][8], int tx, int ty){
    const float* pp = p_s + ty*4*PSTR;
    #pragma unroll 1
    for (int e = 0; e < DDIM; e += 4){
        float4 pv[4];
        #pragma unroll
        for (int i = 0; i < 4; i++) pv[i] = *(const float4*)&pp[i*PSTR + e];
        #pragma unroll
        for (int j = 0; j < 8; j++){
            float4 w = *(const float4*)&wa[(tx + 16*j)*WSTR + e];
            #pragma unroll
            for (int i = 0; i < 4; i++){
                acc[i][j] = fmaf(pv[i].x, w.x, acc[i][j]);
                acc[i][j] = fmaf(pv[i].y, w.y, acc[i][j]);
                acc[i][j] = fmaf(pv[i].z, w.z, acc[i][j]);
                acc[i][j] = fmaf(pv[i].w, w.w, acc[i][j]);
            }
        }
    }
}

// ---------------- Kernel 0: pre-split weights to bf16 hi/lo ----------------
__global__ void k0_prep(const float* __restrict__ lpw, const float* __restrict__ lgw,
                        const float* __restrict__ rpw, const float* __restrict__ rgw,
                        const float* __restrict__ ogw)
{
    const float* srcs[5] = {lpw, lgw, rpw, rgw, ogw};
    int m = blockIdx.y;
    int idx = blockIdx.x * 256 + threadIdx.x;   // 0..16383
    float v = srcs[m][idx];
    __nv_bfloat16 h = __float2bfloat16(v);
    g_wh[m*16384 + idx] = h;
    g_wl[m*16384 + idx] = __float2bfloat16(v - __bfloat162float(h));
}

// ---------------- Kernel 1: LN + 5 gated projections (tensor-core) ----------------
// CTA = 128 pair rows. smem: A_hi[0,32K) A_lo[32K,64K) W[64K,192K) (4 x 32K slots).
// pstage/st alias the W region.
__global__ void __launch_bounds__(256, 1)
k1_tc(const float* __restrict__ pair, const float* __restrict__ mask,
      const float* __restrict__ nw,  const float* __restrict__ nb,
      const float* __restrict__ lpb, const float* __restrict__ lgb,
      const float* __restrict__ rpb, const float* __restrict__ rgb,
      const float* __restrict__ ogb)
{
    extern __shared__ char smraw[];
    char* smb = (char*)(((uintptr_t)smraw + 1023) & ~(uintptr_t)1023);
    const uint32_t sb = smem_u32(smb);
    float*    pstage = (float*)(smb + 65536);
    uint32_t* st     = (uint32_t*)(smb + 65536);
    float*    stf    = (float*)(smb + 65536);
    __shared__ float mask_s[128];
    __shared__ float pb_s[128], gb_s[128];

    const int tid  = threadIdx.x;
    const int lane = tid & 31;
    const int wid  = tid >> 5;
    const int wm   = wid & 1;
    const int wn   = wid >> 1;
    const int row0 = blockIdx.x * 128;
    const int i_idx = row0 >> 9;
    const int k0    = row0 & 511;

    // ---- load pair fp32 (coalesced) ----
    for (int idx = tid; idx < 128*128/4; idx += 256)
        *(float4*)&pstage[idx << 2] = *(const float4*)&pair[(size_t)row0*DDIM + (idx << 2)];
    if (tid < 128) mask_s[tid] = mask[row0 + tid];
    __syncthreads();

    // ---- LN (2 threads/row) -> split bf16 A, swizzled ----
    {
        int row = tid >> 1, half = tid & 1;
        const float* pr = pstage + row*128 + half*64;
        float s = 0.f, ss = 0.f;
        #pragma unroll
        for (int q = 0; q < 16; q++){
            float4 v = *(const float4*)&pr[q*4];
            s  += v.x + v.y + v.z + v.w;
            ss += v.x*v.x + v.y*v.y + v.z*v.z + v.w*v.w;
        }
        s  += __shfl_xor_sync(0xFFFFFFFFu, s, 1);
        ss += __shfl_xor_sync(0xFFFFFFFFu, ss, 1);
        float m  = s * (1.f/128.f);
        float vv = fmaxf(ss * (1.f/128.f) - m*m, 0.f);
        float iv = rsqrtf(vv + 1e-5f);
        #pragma unroll
        for (int q = 0; q < 8; q++){
            int e = half*64 + q*8;
            uint4 hv, lv;
            unsigned short* hp = (unsigned short*)&hv;
            unsigned short* lp = (unsigned short*)&lv;
            #pragma unroll
            for (int t = 0; t < 8; t++){
                float y = (pr[q*8 + t] - m)*iv*nw[e + t] + nb[e + t];
                uint32_t pk = split_pack(y);
                hp[t] = (unsigned short)(pk & 0xFFFFu);
                lp[t] = (unsigned short)(pk >> 16);
            }
            int c = half*8 + q;
            uint32_t off = (uint32_t)(row*256 + (((c ^ (row & 7)) << 4)));
            *(uint4*)(smb + off)         = hv;
            *(uint4*)(smb + 32768 + off) = lv;
        }
    }
    __syncthreads();   // pstage consumed; A ready

    // weight loader into slot (0..3)
    auto loadW = [&](const __nv_bfloat16* src, int slot){
        #pragma unroll
        for (int t = 0; t < 8; t++){
            int idx = tid + (t << 8);          // 0..2047 16B chunks
            int d = idx >> 4;
            int c = idx & 15;
            uint32_t dst = sb + 65536 + (slot << 15) + (uint32_t)(d*256 + (((c ^ (d & 7)) << 4)));
            CP_ASYNC16(dst, (const char*)src + (idx << 4));
        }
    };

    // ---- passes A (left) and B (right): value+gate pair ----
    #pragma unroll 1
    for (int pa = 0; pa < 2; pa++){
        const int matp = pa*2, matg = pa*2 + 1;
        loadW(g_wh + matp*16384, 0);
        loadW(g_wl + matp*16384, 1);
        loadW(g_wh + matg*16384, 2);
        loadW(g_wl + matg*16384, 3);
        CP_COMMIT();
        if (tid < 128){
            pb_s[tid] = pa ? rpb[tid] : lpb[tid];
            gb_s[tid] = pa ? rgb[tid] : lgb[tid];
        }
        CP_WAIT0();
        __syncthreads();

        float accp[4][4][4], accg[4][4][4];
        #pragma unroll
        for (int a = 0; a < 4; a++)
            #pragma unroll
            for (int b = 0; b < 4; b++)
                #pragma unroll
                for (int q = 0; q < 4; q++){ accp[a][b][q] = 0.f; accg[a][b][q] = 0.f; }

        #pragma unroll 1
        for (int kk = 0; kk < 8; kk++){
            uint32_t ah[4][4], al[4][4];
            #pragma unroll
            for (int mt = 0; mt < 4; mt++){
                int r = wm*64 + mt*16 + (lane & 15);
                int c = kk*2 + (lane >> 4);
                uint32_t off = (uint32_t)(r*256 + (((c ^ (r & 7)) << 4)));
                ldsm4(ah[mt], sb + off);
                ldsm4(al[mt], sb + 32768 + off);
            }
            uint32_t bph[4][2], bpl[4][2], bgh[4][2], bgl[4][2];
            #pragma unroll
            for (int nt = 0; nt < 4; nt++){
                int l = lane & 15;
                int n = wn*32 + nt*8 + (l & 7);
                int c = kk*2 + (l >> 3);
                uint32_t off = (uint32_t)(n*256 + (((c ^ (n & 7)) << 4)));
                ldsm2(bph[nt], sb + 65536 + off);
                ldsm2(bpl[nt], sb + 65536 + 32768 + off);
                ldsm2(bgh[nt], sb + 131072 + off);
                ldsm2(bgl[nt], sb + 131072 + 32768 + off);
            }
            #pragma unroll
            for (int mt = 0; mt < 4; mt++)
                #pragma unroll
                for (int nt = 0; nt < 4; nt++){
                    mma_bf16(accp[mt][nt], ah[mt], bph[nt]);
                    mma_bf16(accp[mt][nt], ah[mt], bpl[nt]);
                    mma_bf16(accp[mt][nt], al[mt], bph[nt]);
                    mma_bf16(accg[mt][nt], ah[mt], bgh[nt]);
                    mma_bf16(accg[mt][nt], ah[mt], bgl[nt]);
                    mma_bf16(accg[mt][nt], al[mt], bgh[nt]);
                }
        }
        __syncthreads();   // done reading W; st may overwrite

        // epilogue: bias + sigmoid + mask -> packed st[m][n]
        #pragma unroll
        for (int mt = 0; mt < 4; mt++)
            #pragma unroll
            for (int nt = 0; nt < 4; nt++)
                #pragma unroll
                for (int q = 0; q < 4; q++){
                    int m = wm*64 + mt*16 + (lane >> 2) + ((q >> 1) << 3);
                    int n = wn*32 + nt*8 + ((lane & 3) << 1) + (q & 1);
                    float x = accp[mt][nt][q] + pb_s[n];
                    float g = accg[mt][nt][q] + gb_s[n];
                    st[m*129 + n] = split_pack(x * sigf(g) * mask_s[m]);
                }
        __syncthreads();

        // transpose write: [d][i][k]
        {
            __nv_bfloat16* ghi = pa ? g_rT_hi : g_lT_hi;
            __nv_bfloat16* glo = pa ? g_rT_lo : g_lT_lo;
            int dd = tid >> 1, half = tid & 1;
            uint4 oh[8], ol[8];
            unsigned short* hp = (unsigned short*)oh;
            unsigned short* lp = (unsigned short*)ol;
            #pragma unroll
            for (int kk = 0; kk < 64; kk++){
                uint32_t pk = st[(half*64 + kk)*129 + dd];
                hp[kk] = (unsigned short)(pk & 0xFFFFu);
                lp[kk] = (unsigned short)(pk >> 16);
            }
            size_t gb = ((size_t)dd*NDIM + i_idx)*NDIM + k0 + half*64;
            #pragma unroll
            for (int q = 0; q < 8; q++){
                *(uint4*)&ghi[gb + q*8] = oh[q];
                *(uint4*)&glo[gb + q*8] = ol[q];
            }
        }
        __syncthreads();
    }

    // ---- pass C: output gate ----
    loadW(g_wh + 4*16384, 0);
    loadW(g_wl + 4*16384, 1);
    CP_COMMIT();
    if (tid < 128) pb_s[tid] = ogb[tid];
    CP_WAIT0();
    __syncthreads();
    {
        float acc[4][4][4];
        #pragma unroll
        for (int a = 0; a < 4; a++)
            #pragma unroll
            for (int b = 0; b < 4; b++)
                #pragma unroll
                for (int q = 0; q < 4; q++) acc[a][b][q] = 0.f;

        #pragma unroll 1
        for (int kk = 0; kk < 8; kk++){
            uint32_t ah[4][4], al[4][4];
            #pragma unroll
            for (int mt = 0; mt < 4; mt++){
                int r = wm*64 + mt*16 + (lane & 15);
                int c = kk*2 + (lane >> 4);
                uint32_t off = (uint32_t)(r*256 + (((c ^ (r & 7)) << 4)));
                ldsm4(ah[mt], sb + off);
                ldsm4(al[mt], sb + 32768 + off);
            }
            uint32_t bh[4][2], bl[4][2];
            #pragma unroll
            for (int nt = 0; nt < 4; nt++){
                int l = lane & 15;
                int n = wn*32 + nt*8 + (l & 7);
                int c = kk*2 + (l >> 3);
                uint32_t off = (uint32_t)(n*256 + (((c ^ (n & 7)) << 4)));
                ldsm2(bh[nt], sb + 65536 + off);
                ldsm2(bl[nt], sb + 65536 + 32768 + off);
            }
            #pragma unroll
            for (int mt = 0; mt < 4; mt++)
                #pragma unroll
                for (int nt = 0; nt < 4; nt++){
                    mma_bf16(acc[mt][nt], ah[mt], bh[nt]);
                    mma_bf16(acc[mt][nt], ah[mt], bl[nt]);
                    mma_bf16(acc[mt][nt], al[mt], bh[nt]);
                }
        }
        __syncthreads();
        #pragma unroll
        for (int mt = 0; mt < 4; mt++)
            #pragma unroll
            for (int nt = 0; nt < 4; nt++)
                #pragma unroll
                for (int q = 0; q < 4; q++){
                    int m = wm*64 + mt*16 + (lane >> 2) + ((q >> 1) << 3);
                    int n = wn*32 + nt*8 + ((lane & 3) << 1) + (q & 1);
                    stf[m*129 + n] = sigf(acc[mt][nt][q] + pb_s[n]);
                }
        __syncthreads();
        for (int idx = tid; idx < 128*32; idx += 256){
            int m  = idx >> 5;
            int d4 = (idx & 31) << 2;
            float4 v;
            v.x = stf[m*129 + d4 + 0];
            v.y = stf[m*129 + d4 + 1];
            v.z = stf[m*129 + d4 + 2];
            v.w = stf[m*129 + d4 + 3];
            *(float4*)&g_gate[(size_t)(row0 + m)*DDIM + d4] = v;
        }
    }
}

// ---------------- Kernel 2: mma.sync split-bf16 batched einsum ----------------
#define K2_BUF 65536

__global__ void __launch_bounds__(256, 1)
k2_mma()
{
    extern __shared__ char smraw[];
    char* smb = (char*)(((uintptr_t)smraw + 127) & ~(uintptr_t)127);
    const uint32_t sb = smem_u32(smb);

    const int tid  = threadIdx.x;
    const int lane = tid & 31;
    const int wid  = tid >> 5;
    const int d    = blockIdx.y;
    const int i0   = (blockIdx.x >> 2) * 128;
    const int j0   = (blockIdx.x & 3) * 128;
    const int wm   = wid & 1;
    const int wn   = wid >> 1;

    auto load_chunk = [&](int kc, int b){
        #pragma unroll
        for (int t = 0; t < 16; t++){
            int idx  = tid + (t << 8);
            int tile = idx >> 10;
            int r    = (idx >> 3) & 127;
            int c    = idx & 7;
            const __nv_bfloat16* src = (tile == 0) ? g_lT_hi :
                                       (tile == 1) ? g_lT_lo :
                                       (tile == 2) ? g_rT_hi : g_rT_lo;
            int rb = ((tile & 2) ? j0 : i0) + r;
            const void* gp = &src[((size_t)d*NDIM + rb)*NDIM + kc + (c << 3)];
            uint32_t dst = sb + (b << 16) + (tile << 14) + (r << 7) + (((c ^ (r & 7)) << 4));
            CP_ASYNC16(dst, gp);
        }
        CP_COMMIT();
    };

    float acc[4][4][4];
    #pragma unroll
    for (int a = 0; a < 4; a++)
        #pragma unroll
        for (int b = 0; b < 4; b++)
            #pragma unroll
            for (int q = 0; q < 4; q++) acc[a][b][q] = 0.f;

    load_chunk(0, 0);
    load_chunk(64, 1);

    #pragma unroll 1
    for (int t = 0; t < 8; t++){
        if (t == 7) asm volatile("cp.async.wait_group 0;" ::: "memory");
        else        asm volatile("cp.async.wait_group 1;" ::: "memory");
        __syncthreads();

        const uint32_t base = sb + ((t & 1) << 16);
        #pragma unroll
        for (int kk = 0; kk < 4; kk++){
            uint32_t ah[4][4], al[4][4], bh[4][2], bl[4][2];
            #pragma unroll
            for (int mt = 0; mt < 4; mt++){
                int m = wm*64 + mt*16 + (lane & 15);
                int c = kk*2 + (lane >> 4);
                uint32_t off = (uint32_t)((m << 7) + (((c ^ (m & 7)) << 4)));
                ldsm4(ah[mt], base + off);
                ldsm4(al[mt], base + 16384 + off);
            }
            #pragma unroll
            for (int nt = 0; nt < 4; nt++){
                int l = lane & 15;
                int n = wn*32 + nt*8 + (l & 7);
                int c = kk*2 + (l >> 3);
                uint32_t off = (uint32_t)((n << 7) + (((c ^ (n & 7)) << 4)));
                ldsm2(bh[nt], base + 32768 + off);
                ldsm2(bl[nt], base + 49152 + off);
            }
            #pragma unroll
            for (int mt = 0; mt < 4; mt++)
                #pragma unroll
                for (int nt = 0; nt < 4; nt++){
                    mma_bf16(acc[mt][nt], ah[mt], bh[nt]);
                    mma_bf16(acc[mt][nt], ah[mt], bl[nt]);
                    mma_bf16(acc[mt][nt], al[mt], bh[nt]);
                }
        }
        __syncthreads();
        if (t + 2 < 8) load_chunk((t + 2)*64, t & 1);
    }

    #pragma unroll
    for (int mt = 0; mt < 4; mt++){
        int r0 = i0 + wm*64 + mt*16 + (lane >> 2);
        #pragma unroll
        for (int nt = 0; nt < 4; nt++){
            int c0 = j0 + wn*32 + nt*8 + (lane & 3)*2;
            float* p0 = &g_accT[((size_t)d*NDIM + r0)*NDIM + c0];
            float* p1 = &g_accT[((size_t)d*NDIM + r0 + 8)*NDIM + c0];
            p0[0] = acc[mt][nt][0]; p0[1] = acc[mt][nt][1];
            p1[0] = acc[mt][nt][2]; p1[1] = acc[mt][nt][3];
        }
    }
}

// ---------------- Kernel 3: LN(accT) @ opw.T + opb, times gate ----------------
__global__ void __launch_bounds__(THREADS)
k3_out(const float* __restrict__ onw, const float* __restrict__ onb,
       const float* __restrict__ opw, const float* __restrict__ opb,
       float* __restrict__ out)
{
    extern __shared__ float sm[];
    float* p_s = sm;
    float* wa  = sm + R1*PSTR;
    __shared__ float sred[4][64];
    __shared__ float qred[4][64];
    __shared__ float mean_s[64], inv_s[64];

    const int tid  = threadIdx.x;
    const int row0 = blockIdx.x * R1;
    const int i_idx = row0 >> 9;
    const int j0    = row0 & 511;

    for (int idx = tid; idx < R1*DDIM/4; idx += THREADS){
        int dd = idx >> 4;
        int j4 = (idx & 15) << 2;
        float4 v = *(const float4*)&g_accT[((size_t)dd*NDIM + i_idx)*NDIM + j0 + j4];
        p_s[(j4+0)*PSTR + dd] = v.x;
        p_s[(j4+1)*PSTR + dd] = v.y;
        p_s[(j4+2)*PSTR + dd] = v.z;
        p_s[(j4+3)*PSTR + dd] = v.w;
    }
    __syncthreads();
    {
        int r = tid & 63, q = tid >> 6;
        float s = 0.f, ss = 0.f;
        #pragma unroll
        for (int t = 0; t < 8; t++){
            float4 v = *(const float4*)&p_s[r*PSTR + q*32 + t*4];
            s  += v.x + v.y + v.z + v.w;
            ss += v.x*v.x + v.y*v.y + v.z*v.z + v.w*v.w;
        }
        sred[q][r] = s; qred[q][r] = ss;
    }
    __syncthreads();
    if (tid < 64){
        int r = tid;
        float S  = sred[0][r] + sred[1][r] + sred[2][r] + sred[3][r];
        float SS = qred[0][r] + qred[1][r] + qred[2][r] + qred[3][r];
        float m  = S * (1.f/DDIM);
        float v  = fmaxf(SS * (1.f/DDIM) - m*m, 0.f);
        mean_s[r] = m;
        inv_s[r]  = rsqrtf(v + 1e-5f);
    }
    __syncthreads();
    for (int idx = tid; idx < R1*DDIM/4; idx += THREADS){
        int r = idx >> 5;
        int e = (idx & 31) << 2;
        float4 v  = *(float4*)&p_s[r*PSTR + e];
        float4 w4 = *(const float4*)&onw[e];
        float4 b4 = *(const float4*)&onb[e];
        float m = mean_s[r], iv = inv_s[r];
        v.x = (v.x - m)*iv*w4.x + b4.x;
        v.y = (v.y - m)*iv*w4.y + b4.y;
        v.z = (v.z - m)*iv*w4.z + b4.z;
        v.w = (v.w - m)*iv*w4.w + b4.w;
        *(float4*)&p_s[r*PSTR + e] = v;
    }
    __syncthreads();
    load_w(opw, wa, tid);
    __syncthreads();

    const int tx = tid & 15, ty = tid >> 4;
    float acc[4][8];
    #pragma unroll
    for (int i = 0; i < 4; i++)
        #pragma unroll
        for (int j = 0; j < 8; j++) acc[i][j] = 0.f;
    gemm_one(p_s, wa, acc, tx, ty);

    #pragma unroll
    for (int i = 0; i < 4; i++){
        int rr = row0 + ty*4 + i;
        #pragma unroll
        for (int j = 0; j < 8; j++){
            int d = tx + 16*j;
            float x = acc[i][j] + opb[d];
            out[(size_t)rr*DDIM + d] = x * g_gate[(size_t)rr*DDIM + d];
        }
    }
}

extern "C" void kernel_launch(void* const* d_in, const int* in_sizes, int n_in,
                              void* d_out, int out_size)
{
    const float* pair = (const float*)d_in[0];
    const float* mask = (const float*)d_in[1];
    const float* nw   = (const float*)d_in[2];
    const float* nb   = (const float*)d_in[3];
    const float* lpw  = (const float*)d_in[4];
    const float* lpb  = (const float*)d_in[5];
    const float* lgw  = (const float*)d_in[6];
    const float* lgb  = (const float*)d_in[7];
    const float* rpw  = (const float*)d_in[8];
    const float* rpb  = (const float*)d_in[9];
    const float* rgw  = (const float*)d_in[10];
    const float* rgb  = (const float*)d_in[11];
    const float* onw  = (const float*)d_in[12];
    const float* onb  = (const float*)d_in[13];
    const float* opw  = (const float*)d_in[14];
    const float* opb  = (const float*)d_in[15];
    const float* ogw  = (const float*)d_in[16];
    const float* ogb  = (const float*)d_in[17];
    float* out = (float*)d_out;

    const int smem1 = 196608 + 1024;
    const int smem2 = 2*K2_BUF + 256;
    const int smem3 = (R1*PSTR + 1*DDIM*WSTR) * (int)sizeof(float);
    cudaFuncSetAttribute(k1_tc,  cudaFuncAttributeMaxDynamicSharedMemorySize, smem1);
    cudaFuncSetAttribute(k2_mma, cudaFuncAttributeMaxDynamicSharedMemorySize, smem2);
    cudaFuncSetAttribute(k3_out, cudaFuncAttributeMaxDynamicSharedMemorySize, smem3);

    k0_prep<<<dim3(64, 5), 256>>>(lpw, lgw, rpw, rgw, ogw);

    k1_tc<<<NN/128, 256, smem1>>>(pair, mask, nw, nb, lpb, lgb, rpb, rgb, ogb);

    dim3 g2(16, 128);
    k2_mma<<<g2, 256, smem2>>>();

    k3_out<<<NN/R1, THREADS, smem3>>>(onw, onb, opw, opb, out);
}

// round 6
// speedup vs baseline: 2.5103x; 1.1362x over previous
#include <cuda_runtime.h>
#include <cuda_bf16.h>
#include <cstdint>

#define NDIM 512
#define DDIM 128
#define NN (NDIM*NDIM)
#define THREADS 256

// ---------------- scratch (device globals; no allocation allowed) ----------------
__device__ __align__(256) __nv_bfloat16 g_lT_hi[(size_t)DDIM*NDIM*NDIM];
__device__ __align__(256) __nv_bfloat16 g_lT_lo[(size_t)DDIM*NDIM*NDIM];
__device__ __align__(256) __nv_bfloat16 g_rT_hi[(size_t)DDIM*NDIM*NDIM];
__device__ __align__(256) __nv_bfloat16 g_rT_lo[(size_t)DDIM*NDIM*NDIM];
__device__ __align__(256) float g_gate[(size_t)NN*DDIM];
__device__ __align__(256) float g_accT[(size_t)DDIM*NDIM*NDIM];   // [d][i][j]
// pre-split weights: 0=lp 1=lg 2=rp 3=rg 4=og 5=op
__device__ __align__(256) __nv_bfloat16 g_wh[6*16384];
__device__ __align__(256) __nv_bfloat16 g_wl[6*16384];

__device__ __forceinline__ float sigf(float x){ return 1.0f/(1.0f+__expf(-x)); }

__device__ __forceinline__ uint32_t split_pack(float v){
    __nv_bfloat16 h = __float2bfloat16(v);
    float hf = __bfloat162float(h);
    __nv_bfloat16 l = __float2bfloat16(v - hf);
    return (uint32_t)__bfloat16_as_ushort(h) | ((uint32_t)__bfloat16_as_ushort(l) << 16);
}

__device__ __forceinline__ uint32_t smem_u32(const void* p){
    uint32_t a;
    asm("{ .reg .u64 t; cvta.to.shared.u64 t, %1; cvt.u32.u64 %0, t; }" : "=r"(a) : "l"(p));
    return a;
}

// ---------------- baseline-PTX tensor-core helpers ----------------
__device__ __forceinline__ void ldsm4(uint32_t (&r)[4], uint32_t a){
    asm volatile("ldmatrix.sync.aligned.m8n8.x4.shared.b16 {%0,%1,%2,%3}, [%4];"
        : "=r"(r[0]), "=r"(r[1]), "=r"(r[2]), "=r"(r[3]) : "r"(a));
}
__device__ __forceinline__ void ldsm2(uint32_t (&r)[2], uint32_t a){
    asm volatile("ldmatrix.sync.aligned.m8n8.x2.shared.b16 {%0,%1}, [%2];"
        : "=r"(r[0]), "=r"(r[1]) : "r"(a));
}
__device__ __forceinline__ void mma_bf16(float (&c)[4], const uint32_t (&a)[4], const uint32_t (&b)[2]){
    asm volatile("mma.sync.aligned.m16n8k16.row.col.f32.bf16.bf16.f32 "
        "{%0,%1,%2,%3}, {%4,%5,%6,%7}, {%8,%9}, {%0,%1,%2,%3};"
        : "+f"(c[0]), "+f"(c[1]), "+f"(c[2]), "+f"(c[3])
        : "r"(a[0]), "r"(a[1]), "r"(a[2]), "r"(a[3]), "r"(b[0]), "r"(b[1]));
}
#define CP_ASYNC16(dst, src) \
    asm volatile("cp.async.cg.shared.global [%0], [%1], 16;" :: "r"(dst), "l"(src) : "memory")
#define CP_COMMIT() asm volatile("cp.async.commit_group;" ::: "memory")
#define CP_WAIT0()  asm volatile("cp.async.wait_group 0;" ::: "memory")

// ---------------- Kernel 0: pre-split weights to bf16 hi/lo ----------------
__global__ void k0_prep(const float* __restrict__ lpw, const float* __restrict__ lgw,
                        const float* __restrict__ rpw, const float* __restrict__ rgw,
                        const float* __restrict__ ogw, const float* __restrict__ opw)
{
    const float* srcs[6] = {lpw, lgw, rpw, rgw, ogw, opw};
    int m = blockIdx.y;
    int idx = blockIdx.x * 256 + threadIdx.x;   // 0..16383
    float v = srcs[m][idx];
    __nv_bfloat16 h = __float2bfloat16(v);
    g_wh[m*16384 + idx] = h;
    g_wl[m*16384 + idx] = __float2bfloat16(v - __bfloat162float(h));
}

// ---------------- Kernel 1: LN + 5 gated projections (tensor-core) ----------------
__global__ void __launch_bounds__(256, 1)
k1_tc(const float* __restrict__ pair, const float* __restrict__ mask,
      const float* __restrict__ nw,  const float* __restrict__ nb,
      const float* __restrict__ lpb, const float* __restrict__ lgb,
      const float* __restrict__ rpb, const float* __restrict__ rgb,
      const float* __restrict__ ogb)
{
    extern __shared__ char smraw[];
    char* smb = (char*)(((uintptr_t)smraw + 1023) & ~(uintptr_t)1023);
    const uint32_t sb = smem_u32(smb);
    float*    pstage = (float*)(smb + 65536);
    uint32_t* st     = (uint32_t*)(smb + 65536);
    float*    stf    = (float*)(smb + 65536);
    __shared__ float mask_s[128];
    __shared__ float pb_s[128], gb_s[128];

    const int tid  = threadIdx.x;
    const int lane = tid & 31;
    const int wid  = tid >> 5;
    const int wm   = wid & 1;
    const int wn   = wid >> 1;
    const int row0 = blockIdx.x * 128;
    const int i_idx = row0 >> 9;
    const int k0    = row0 & 511;

    for (int idx = tid; idx < 128*128/4; idx += 256)
        *(float4*)&pstage[idx << 2] = *(const float4*)&pair[(size_t)row0*DDIM + (idx << 2)];
    if (tid < 128) mask_s[tid] = mask[row0 + tid];
    __syncthreads();

    {
        int row = tid >> 1, half = tid & 1;
        const float* pr = pstage + row*128 + half*64;
        float s = 0.f, ss = 0.f;
        #pragma unroll
        for (int q = 0; q < 16; q++){
            float4 v = *(const float4*)&pr[q*4];
            s  += v.x + v.y + v.z + v.w;
            ss += v.x*v.x + v.y*v.y + v.z*v.z + v.w*v.w;
        }
        s  += __shfl_xor_sync(0xFFFFFFFFu, s, 1);
        ss += __shfl_xor_sync(0xFFFFFFFFu, ss, 1);
        float m  = s * (1.f/128.f);
        float vv = fmaxf(ss * (1.f/128.f) - m*m, 0.f);
        float iv = rsqrtf(vv + 1e-5f);
        #pragma unroll
        for (int q = 0; q < 8; q++){
            int e = half*64 + q*8;
            uint4 hv, lv;
            unsigned short* hp = (unsigned short*)&hv;
            unsigned short* lp = (unsigned short*)&lv;
            #pragma unroll
            for (int t = 0; t < 8; t++){
                float y = (pr[q*8 + t] - m)*iv*nw[e + t] + nb[e + t];
                uint32_t pk = split_pack(y);
                hp[t] = (unsigned short)(pk & 0xFFFFu);
                lp[t] = (unsigned short)(pk >> 16);
            }
            int c = half*8 + q;
            uint32_t off = (uint32_t)(row*256 + (((c ^ (row & 7)) << 4)));
            *(uint4*)(smb + off)         = hv;
            *(uint4*)(smb + 32768 + off) = lv;
        }
    }
    __syncthreads();

    auto loadW = [&](const __nv_bfloat16* src, int slot){
        #pragma unroll
        for (int t = 0; t < 8; t++){
            int idx = tid + (t << 8);
            int d = idx >> 4;
            int c = idx & 15;
            uint32_t dst = sb + 65536 + (slot << 15) + (uint32_t)(d*256 + (((c ^ (d & 7)) << 4)));
            CP_ASYNC16(dst, (const char*)src + (idx << 4));
        }
    };

    #pragma unroll 1
    for (int pa = 0; pa < 2; pa++){
        const int matp = pa*2, matg = pa*2 + 1;
        loadW(g_wh + matp*16384, 0);
        loadW(g_wl + matp*16384, 1);
        loadW(g_wh + matg*16384, 2);
        loadW(g_wl + matg*16384, 3);
        CP_COMMIT();
        if (tid < 128){
            pb_s[tid] = pa ? rpb[tid] : lpb[tid];
            gb_s[tid] = pa ? rgb[tid] : lgb[tid];
        }
        CP_WAIT0();
        __syncthreads();

        float accp[4][4][4], accg[4][4][4];
        #pragma unroll
        for (int a = 0; a < 4; a++)
            #pragma unroll
            for (int b = 0; b < 4; b++)
                #pragma unroll
                for (int q = 0; q < 4; q++){ accp[a][b][q] = 0.f; accg[a][b][q] = 0.f; }

        #pragma unroll 1
        for (int kk = 0; kk < 8; kk++){
            uint32_t ah[4][4], al[4][4];
            #pragma unroll
            for (int mt = 0; mt < 4; mt++){
                int r = wm*64 + mt*16 + (lane & 15);
                int c = kk*2 + (lane >> 4);
                uint32_t off = (uint32_t)(r*256 + (((c ^ (r & 7)) << 4)));
                ldsm4(ah[mt], sb + off);
                ldsm4(al[mt], sb + 32768 + off);
            }
            uint32_t bph[4][2], bpl[4][2], bgh[4][2], bgl[4][2];
            #pragma unroll
            for (int nt = 0; nt < 4; nt++){
                int l = lane & 15;
                int n = wn*32 + nt*8 + (l & 7);
                int c = kk*2 + (l >> 3);
                uint32_t off = (uint32_t)(n*256 + (((c ^ (n & 7)) << 4)));
                ldsm2(bph[nt], sb + 65536 + off);
                ldsm2(bpl[nt], sb + 65536 + 32768 + off);
                ldsm2(bgh[nt], sb + 131072 + off);
                ldsm2(bgl[nt], sb + 131072 + 32768 + off);
            }
            #pragma unroll
            for (int mt = 0; mt < 4; mt++)
                #pragma unroll
                for (int nt = 0; nt < 4; nt++){
                    mma_bf16(accp[mt][nt], ah[mt], bph[nt]);
                    mma_bf16(accp[mt][nt], ah[mt], bpl[nt]);
                    mma_bf16(accp[mt][nt], al[mt], bph[nt]);
                    mma_bf16(accg[mt][nt], ah[mt], bgh[nt]);
                    mma_bf16(accg[mt][nt], ah[mt], bgl[nt]);
                    mma_bf16(accg[mt][nt], al[mt], bgh[nt]);
                }
        }
        __syncthreads();

        #pragma unroll
        for (int mt = 0; mt < 4; mt++)
            #pragma unroll
            for (int nt = 0; nt < 4; nt++)
                #pragma unroll
                for (int q = 0; q < 4; q++){
                    int m = wm*64 + mt*16 + (lane >> 2) + ((q >> 1) << 3);
                    int n = wn*32 + nt*8 + ((lane & 3) << 1) + (q & 1);
                    float x = accp[mt][nt][q] + pb_s[n];
                    float g = accg[mt][nt][q] + gb_s[n];
                    st[m*129 + n] = split_pack(x * sigf(g) * mask_s[m]);
                }
        __syncthreads();

        {
            __nv_bfloat16* ghi = pa ? g_rT_hi : g_lT_hi;
            __nv_bfloat16* glo = pa ? g_rT_lo : g_lT_lo;
            int dd = tid >> 1, half = tid & 1;
            uint4 oh[8], ol[8];
            unsigned short* hp = (unsigned short*)oh;
            unsigned short* lp = (unsigned short*)ol;
            #pragma unroll
            for (int kk = 0; kk < 64; kk++){
                uint32_t pk = st[(half*64 + kk)*129 + dd];
                hp[kk] = (unsigned short)(pk & 0xFFFFu);
                lp[kk] = (unsigned short)(pk >> 16);
            }
            size_t gb = ((size_t)dd*NDIM + i_idx)*NDIM + k0 + half*64;
            #pragma unroll
            for (int q = 0; q < 8; q++){
                *(uint4*)&ghi[gb + q*8] = oh[q];
                *(uint4*)&glo[gb + q*8] = ol[q];
            }
        }
        __syncthreads();
    }

    // ---- pass C: output gate ----
    loadW(g_wh + 4*16384, 0);
    loadW(g_wl + 4*16384, 1);
    CP_COMMIT();
    if (tid < 128) pb_s[tid] = ogb[tid];
    CP_WAIT0();
    __syncthreads();
    {
        float acc[4][4][4];
        #pragma unroll
        for (int a = 0; a < 4; a++)
            #pragma unroll
            for (int b = 0; b < 4; b++)
                #pragma unroll
                for (int q = 0; q < 4; q++) acc[a][b][q] = 0.f;

        #pragma unroll 1
        for (int kk = 0; kk < 8; kk++){
            uint32_t ah[4][4], al[4][4];
            #pragma unroll
            for (int mt = 0; mt < 4; mt++){
                int r = wm*64 + mt*16 + (lane & 15);
                int c = kk*2 + (lane >> 4);
                uint32_t off = (uint32_t)(r*256 + (((c ^ (r & 7)) << 4)));
                ldsm4(ah[mt], sb + off);
                ldsm4(al[mt], sb + 32768 + off);
            }
            uint32_t bh[4][2], bl[4][2];
            #pragma unroll
            for (int nt = 0; nt < 4; nt++){
                int l = lane & 15;
                int n = wn*32 + nt*8 + (l & 7);
                int c = kk*2 + (l >> 3);
                uint32_t off = (uint32_t)(n*256 + (((c ^ (n & 7)) << 4)));
                ldsm2(bh[nt], sb + 65536 + off);
                ldsm2(bl[nt], sb + 65536 + 32768 + off);
            }
            #pragma unroll
            for (int mt = 0; mt < 4; mt++)
                #pragma unroll
                for (int nt = 0; nt < 4; nt++){
                    mma_bf16(acc[mt][nt], ah[mt], bh[nt]);
                    mma_bf16(acc[mt][nt], ah[mt], bl[nt]);
                    mma_bf16(acc[mt][nt], al[mt], bh[nt]);
                }
        }
        __syncthreads();
        #pragma unroll
        for (int mt = 0; mt < 4; mt++)
            #pragma unroll
            for (int nt = 0; nt < 4; nt++)
                #pragma unroll
                for (int q = 0; q < 4; q++){
                    int m = wm*64 + mt*16 + (lane >> 2) + ((q >> 1) << 3);
                    int n = wn*32 + nt*8 + ((lane & 3) << 1) + (q & 1);
                    stf[m*129 + n] = sigf(acc[mt][nt][q] + pb_s[n]);
                }
        __syncthreads();
        for (int idx = tid; idx < 128*32; idx += 256){
            int m  = idx >> 5;
            int d4 = (idx & 31) << 2;
            float4 v;
            v.x = stf[m*129 + d4 + 0];
            v.y = stf[m*129 + d4 + 1];
            v.z = stf[m*129 + d4 + 2];
            v.w = stf[m*129 + d4 + 3];
            *(float4*)&g_gate[(size_t)(row0 + m)*DDIM + d4] = v;
        }
    }
}

// ---------------- Kernel 2: mma.sync split-bf16 batched einsum ----------------
#define K2_BUF 65536

__global__ void __launch_bounds__(256, 1)
k2_mma()
{
    extern __shared__ char smraw[];
    char* smb = (char*)(((uintptr_t)smraw + 127) & ~(uintptr_t)127);
    const uint32_t sb = smem_u32(smb);

    const int tid  = threadIdx.x;
    const int lane = tid & 31;
    const int wid  = tid >> 5;
    const int d    = blockIdx.y;
    const int i0   = (blockIdx.x >> 2) * 128;
    const int j0   = (blockIdx.x & 3) * 128;
    const int wm   = wid & 1;
    const int wn   = wid >> 1;

    auto load_chunk = [&](int kc, int b){
        #pragma unroll
        for (int t = 0; t < 16; t++){
            int idx  = tid + (t << 8);
            int tile = idx >> 10;
            int r    = (idx >> 3) & 127;
            int c    = idx & 7;
            const __nv_bfloat16* src = (tile == 0) ? g_lT_hi :
                                       (tile == 1) ? g_lT_lo :
                                       (tile == 2) ? g_rT_hi : g_rT_lo;
            int rb = ((tile & 2) ? j0 : i0) + r;
            const void* gp = &src[((size_t)d*NDIM + rb)*NDIM + kc + (c << 3)];
            uint32_t dst = sb + (b << 16) + (tile << 14) + (r << 7) + (((c ^ (r & 7)) << 4));
            CP_ASYNC16(dst, gp);
        }
        CP_COMMIT();
    };

    float acc[4][4][4];
    #pragma unroll
    for (int a = 0; a < 4; a++)
        #pragma unroll
        for (int b = 0; b < 4; b++)
            #pragma unroll
            for (int q = 0; q < 4; q++) acc[a][b][q] = 0.f;

    load_chunk(0, 0);
    load_chunk(64, 1);

    #pragma unroll 1
    for (int t = 0; t < 8; t++){
        if (t == 7) asm volatile("cp.async.wait_group 0;" ::: "memory");
        else        asm volatile("cp.async.wait_group 1;" ::: "memory");
        __syncthreads();

        const uint32_t base = sb + ((t & 1) << 16);
        #pragma unroll
        for (int kk = 0; kk < 4; kk++){
            uint32_t ah[4][4], al[4][4], bh[4][2], bl[4][2];
            #pragma unroll
            for (int mt = 0; mt < 4; mt++){
                int m = wm*64 + mt*16 + (lane & 15);
                int c = kk*2 + (lane >> 4);
                uint32_t off = (uint32_t)((m << 7) + (((c ^ (m & 7)) << 4)));
                ldsm4(ah[mt], base + off);
                ldsm4(al[mt], base + 16384 + off);
            }
            #pragma unroll
            for (int nt = 0; nt < 4; nt++){
                int l = lane & 15;
                int n = wn*32 + nt*8 + (l & 7);
                int c = kk*2 + (l >> 3);
                uint32_t off = (uint32_t)((n << 7) + (((c ^ (n & 7)) << 4)));
                ldsm2(bh[nt], base + 32768 + off);
                ldsm2(bl[nt], base + 49152 + off);
            }
            #pragma unroll
            for (int mt = 0; mt < 4; mt++)
                #pragma unroll
                for (int nt = 0; nt < 4; nt++){
                    mma_bf16(acc[mt][nt], ah[mt], bh[nt]);
                    mma_bf16(acc[mt][nt], ah[mt], bl[nt]);
                    mma_bf16(acc[mt][nt], al[mt], bh[nt]);
                }
        }
        __syncthreads();
        if (t + 2 < 8) load_chunk((t + 2)*64, t & 1);
    }

    #pragma unroll
    for (int mt = 0; mt < 4; mt++){
        int r0 = i0 + wm*64 + mt*16 + (lane >> 2);
        #pragma unroll
        for (int nt = 0; nt < 4; nt++){
            int c0 = j0 + wn*32 + nt*8 + (lane & 3)*2;
            float* p0 = &g_accT[((size_t)d*NDIM + r0)*NDIM + c0];
            float* p1 = &g_accT[((size_t)d*NDIM + r0 + 8)*NDIM + c0];
            p0[0] = acc[mt][nt][0]; p0[1] = acc[mt][nt][1];
            p1[0] = acc[mt][nt][2]; p1[1] = acc[mt][nt][3];
        }
    }
}

// ---------------- Kernel 3 (tensor-core): LN(accT) @ opw.T + opb, times gate ----------------
// smem regions (off the 1024-aligned base):
//   A   [0, 64K)          : split-bf16 LN output, swizzled rows j (k-dim = d)
//   R1  [64K, 64K+67584)  : fp32 accT staging ts[d][j] str 132  -> reused: W hi/lo -> reused: st[j][n] str 132
//   R2  [R1 end, +67584)  : gate tile gt[j][n] str 132 (cp.async prefetched)
#define K3_R1 65536
#define K3_R2 (65536 + 67584)
#define K3_SMEM (K3_R2 + 67584 + 1024)

__global__ void __launch_bounds__(256, 1)
k3_tc(const float* __restrict__ onw, const float* __restrict__ onb,
      const float* __restrict__ opb, float* __restrict__ out)
{
    extern __shared__ char smraw[];
    char* smb = (char*)(((uintptr_t)smraw + 1023) & ~(uintptr_t)1023);
    const uint32_t sb = smem_u32(smb);
    float* ts = (float*)(smb + K3_R1);
    float* st = (float*)(smb + K3_R1);
    float* gt = (float*)(smb + K3_R2);
    __shared__ float pb_s[128];

    const int tid  = threadIdx.x;
    const int lane = tid & 31;
    const int wid  = tid >> 5;
    const int wm   = wid & 1;
    const int wn   = wid >> 1;
    const int i_idx = blockIdx.x >> 2;
    const int j0    = (blockIdx.x & 3) * 128;
    const int row0  = i_idx*NDIM + j0;   // first output row of this CTA

    // prefetch gate tile (independent of everything until epilogue)
    #pragma unroll
    for (int t = 0; t < 16; t++){
        int idx = tid + (t << 8);       // 0..4095 16B chunks
        int j = idx >> 5, c = idx & 31;
        uint32_t dst = sb + K3_R2 + (uint32_t)(j*528 + c*16);
        CP_ASYNC16(dst, (const char*)&g_gate[(size_t)(row0 + j)*DDIM] + c*16);
    }
    CP_COMMIT();

    // load accT tile -> ts[d][j] (stride 132)
    for (int idx = tid; idx < 128*32; idx += 256){
        int d = idx >> 5, j4 = (idx & 31) << 2;
        float4 v = *(const float4*)&g_accT[(size_t)d*NN + row0 + j4];
        ts[d*132 + j4 + 0] = v.x;
        ts[d*132 + j4 + 1] = v.y;
        ts[d*132 + j4 + 2] = v.z;
        ts[d*132 + j4 + 3] = v.w;
    }
    if (tid < 128) pb_s[tid] = opb[tid];
    __syncthreads();

    // LN across d for each j (2 threads per j), emit swizzled split-bf16 A rows j
    {
        int j = tid >> 1, half = tid & 1;
        float s = 0.f, ss = 0.f;
        #pragma unroll
        for (int q = 0; q < 64; q++){
            float v = ts[(half*64 + q)*132 + j];
            s += v; ss += v*v;
        }
        s  += __shfl_xor_sync(0xFFFFFFFFu, s, 1);
        ss += __shfl_xor_sync(0xFFFFFFFFu, ss, 1);
        float m  = s * (1.f/128.f);
        float vv = fmaxf(ss * (1.f/128.f) - m*m, 0.f);
        float iv = rsqrtf(vv + 1e-5f);
        #pragma unroll
        for (int q = 0; q < 8; q++){
            int e = half*64 + q*8;
            uint4 hv, lv;
            unsigned short* hp = (unsigned short*)&hv;
            unsigned short* lp = (unsigned short*)&lv;
            #pragma unroll
            for (int t = 0; t < 8; t++){
                float y = (ts[(e + t)*132 + j] - m)*iv*onw[e + t] + onb[e + t];
                uint32_t pk = split_pack(y);
                hp[t] = (unsigned short)(pk & 0xFFFFu);
                lp[t] = (unsigned short)(pk >> 16);
            }
            int c = half*8 + q;
            uint32_t off = (uint32_t)(j*256 + (((c ^ (j & 7)) << 4)));
            *(uint4*)(smb + off)         = hv;
            *(uint4*)(smb + 32768 + off) = lv;
        }
    }
    __syncthreads();   // ts consumed

    // load opw hi/lo into R1 (swizzled, rows n)
    #pragma unroll
    for (int t = 0; t < 8; t++){
        int idx = tid + (t << 8);
        int d = idx >> 4;
        int c = idx & 15;
        uint32_t off = (uint32_t)(d*256 + (((c ^ (d & 7)) << 4)));
        CP_ASYNC16(sb + K3_R1 + off,          (const char*)(g_wh + 5*16384) + (idx << 4));
        CP_ASYNC16(sb + K3_R1 + 32768 + off,  (const char*)(g_wl + 5*16384) + (idx << 4));
    }
    CP_COMMIT();
    CP_WAIT0();   // waits W and gate
    __syncthreads();

    float acc[4][4][4];
    #pragma unroll
    for (int a = 0; a < 4; a++)
        #pragma unroll
        for (int b = 0; b < 4; b++)
            #pragma unroll
            for (int q = 0; q < 4; q++) acc[a][b][q] = 0.f;

    #pragma unroll 1
    for (int kk = 0; kk < 8; kk++){
        uint32_t ah[4][4], al[4][4];
        #pragma unroll
        for (int mt = 0; mt < 4; mt++){
            int r = wm*64 + mt*16 + (lane & 15);
            int c = kk*2 + (lane >> 4);
            uint32_t off = (uint32_t)(r*256 + (((c ^ (r & 7)) << 4)));
            ldsm4(ah[mt], sb + off);
            ldsm4(al[mt], sb + 32768 + off);
        }
        uint32_t bh[4][2], bl[4][2];
        #pragma unroll
        for (int nt = 0; nt < 4; nt++){
            int l = lane & 15;
            int n = wn*32 + nt*8 + (l & 7);
            int c = kk*2 + (l >> 3);
            uint32_t off = (uint32_t)(n*256 + (((c ^ (n & 7)) << 4)));
            ldsm2(bh[nt], sb + K3_R1 + off);
            ldsm2(bl[nt], sb + K3_R1 + 32768 + off);
        }
        #pragma unroll
        for (int mt = 0; mt < 4; mt++)
            #pragma unroll
            for (int nt = 0; nt < 4; nt++){
                mma_bf16(acc[mt][nt], ah[mt], bh[nt]);
                mma_bf16(acc[mt][nt], ah[mt], bl[nt]);
                mma_bf16(acc[mt][nt], al[mt], bh[nt]);
            }
    }
    __syncthreads();   // W reads done; st may overwrite R1

    // epilogue: (acc + opb) * gate -> st[j][n] (stride 132)
    #pragma unroll
    for (int mt = 0; mt < 4; mt++)
        #pragma unroll
        for (int nt = 0; nt < 4; nt++)
            #pragma unroll
            for (int q = 0; q < 4; q++){
                int j = wm*64 + mt*16 + (lane >> 2) + ((q >> 1) << 3);
                int n = wn*32 + nt*8 + ((lane & 3) << 1) + (q & 1);
                float x = acc[mt][nt][q] + pb_s[n];
                st[j*132 + n] = x * gt[j*132 + n];
            }
    __syncthreads();

    // coalesced write
    for (int idx = tid; idx < 128*32; idx += 256){
        int j  = idx >> 5;
        int n4 = (idx & 31) << 2;
        float4 v;
        v.x = st[j*132 + n4 + 0];
        v.y = st[j*132 + n4 + 1];
        v.z = st[j*132 + n4 + 2];
        v.w = st[j*132 + n4 + 3];
        *(float4*)&out[(size_t)(row0 + j)*DDIM + n4] = v;
    }
}

extern "C" void kernel_launch(void* const* d_in, const int* in_sizes, int n_in,
                              void* d_out, int out_size)
{
    const float* pair = (const float*)d_in[0];
    const float* mask = (const float*)d_in[1];
    const float* nw   = (const float*)d_in[2];
    const float* nb   = (const float*)d_in[3];
    const float* lpw  = (const float*)d_in[4];
    const float* lpb  = (const float*)d_in[5];
    const float* lgw  = (const float*)d_in[6];
    const float* lgb  = (const float*)d_in[7];
    const float* rpw  = (const float*)d_in[8];
    const float* rpb  = (const float*)d_in[9];
    const float* rgw  = (const float*)d_in[10];
    const float* rgb  = (const float*)d_in[11];
    const float* onw  = (const float*)d_in[12];
    const float* onb  = (const float*)d_in[13];
    const float* opw  = (const float*)d_in[14];
    const float* opb  = (const float*)d_in[15];
    const float* ogw  = (const float*)d_in[16];
    const float* ogb  = (const float*)d_in[17];
    float* out = (float*)d_out;

    const int smem1 = 196608 + 1024;
    const int smem2 = 2*K2_BUF + 256;
    const int smem3 = K3_SMEM;
    cudaFuncSetAttribute(k1_tc,  cudaFuncAttributeMaxDynamicSharedMemorySize, smem1);
    cudaFuncSetAttribute(k2_mma, cudaFuncAttributeMaxDynamicSharedMemorySize, smem2);
    cudaFuncSetAttribute(k3_tc,  cudaFuncAttributeMaxDynamicSharedMemorySize, smem3);

    k0_prep<<<dim3(64, 6), 256>>>(lpw, lgw, rpw, rgw, ogw, opw);

    k1_tc<<<NN/128, 256, smem1>>>(pair, mask, nw, nb, lpb, lgb, rpb, rgb, ogb);

    dim3 g2(16, 128);
    k2_mma<<<g2, 256, smem2>>>();

    k3_tc<<<NN/128, 256, smem3>>>(onw, onb, opb, out);
}

// round 7
// speedup vs baseline: 3.2498x; 1.2946x over previous
#include <cuda_runtime.h>
#include <cuda_bf16.h>
#include <cstdint>

#define NDIM 512
#define DDIM 128
#define NN (NDIM*NDIM)

// ---------------- scratch (device globals; no allocation allowed) ----------------
__device__ __align__(256) __nv_bfloat16 g_lT_hi[(size_t)DDIM*NDIM*NDIM];
__device__ __align__(256) __nv_bfloat16 g_lT_lo[(size_t)DDIM*NDIM*NDIM];
__device__ __align__(256) __nv_bfloat16 g_rT_hi[(size_t)DDIM*NDIM*NDIM];
__device__ __align__(256) __nv_bfloat16 g_rT_lo[(size_t)DDIM*NDIM*NDIM];
__device__ __align__(256) float g_gate[(size_t)NN*DDIM];
__device__ __align__(256) float g_accT[(size_t)DDIM*NDIM*NDIM];   // [d][i][j]
// pre-split weights: 0=lp 1=lg 2=rp 3=rg 4=og 5=op
__device__ __align__(256) __nv_bfloat16 g_wh[6*16384];
__device__ __align__(256) __nv_bfloat16 g_wl[6*16384];

__device__ __forceinline__ float sigf(float x){ return 1.0f/(1.0f+__expf(-x)); }

__device__ __forceinline__ uint32_t split_pack(float v){
    __nv_bfloat16 h = __float2bfloat16(v);
    float hf = __bfloat162float(h);
    __nv_bfloat16 l = __float2bfloat16(v - hf);
    return (uint32_t)__bfloat16_as_ushort(h) | ((uint32_t)__bfloat16_as_ushort(l) << 16);
}

__device__ __forceinline__ uint32_t smem_u32(const void* p){
    uint32_t a;
    asm("{ .reg .u64 t; cvta.to.shared.u64 t, %1; cvt.u32.u64 %0, t; }" : "=r"(a) : "l"(p));
    return a;
}

// ---------------- baseline-PTX tensor-core helpers ----------------
__device__ __forceinline__ void ldsm4(uint32_t (&r)[4], uint32_t a){
    asm volatile("ldmatrix.sync.aligned.m8n8.x4.shared.b16 {%0,%1,%2,%3}, [%4];"
        : "=r"(r[0]), "=r"(r[1]), "=r"(r[2]), "=r"(r[3]) : "r"(a));
}
__device__ __forceinline__ void ldsm2(uint32_t (&r)[2], uint32_t a){
    asm volatile("ldmatrix.sync.aligned.m8n8.x2.shared.b16 {%0,%1}, [%2];"
        : "=r"(r[0]), "=r"(r[1]) : "r"(a));
}
__device__ __forceinline__ void mma_bf16(float (&c)[4], const uint32_t (&a)[4], const uint32_t (&b)[2]){
    asm volatile("mma.sync.aligned.m16n8k16.row.col.f32.bf16.bf16.f32 "
        "{%0,%1,%2,%3}, {%4,%5,%6,%7}, {%8,%9}, {%0,%1,%2,%3};"
        : "+f"(c[0]), "+f"(c[1]), "+f"(c[2]), "+f"(c[3])
        : "r"(a[0]), "r"(a[1]), "r"(a[2]), "r"(a[3]), "r"(b[0]), "r"(b[1]));
}
#define CP_ASYNC16(dst, src) \
    asm volatile("cp.async.cg.shared.global [%0], [%1], 16;" :: "r"(dst), "l"(src) : "memory")
#define CP_COMMIT() asm volatile("cp.async.commit_group;" ::: "memory")
#define CP_WAIT0()  asm volatile("cp.async.wait_group 0;" ::: "memory")

// ---------------- Kernel 0: pre-split weights to bf16 hi/lo ----------------
__global__ void k0_prep(const float* __restrict__ lpw, const float* __restrict__ lgw,
                        const float* __restrict__ rpw, const float* __restrict__ rgw,
                        const float* __restrict__ ogw, const float* __restrict__ opw)
{
    const float* srcs[6] = {lpw, lgw, rpw, rgw, ogw, opw};
    int m = blockIdx.y;
    int idx = blockIdx.x * 256 + threadIdx.x;
    float v = srcs[m][idx];
    __nv_bfloat16 h = __float2bfloat16(v);
    g_wh[m*16384 + idx] = h;
    g_wl[m*16384 + idx] = __float2bfloat16(v - __bfloat162float(h));
}

// ================= Kernel 1: LN + 5 gated projections (64-row tiles, 2 CTA/SM) ==========
// smem: A_hi [0,16K) A_lo [16K,32K) ; W hi [32K,64K) W lo [64K,96K)
//       pstage/st overlay the W region (sequenced by syncthreads)
__global__ void __launch_bounds__(256, 2)
k1_tc(const float* __restrict__ pair, const float* __restrict__ mask,
      const float* __restrict__ nw,  const float* __restrict__ nb,
      const float* __restrict__ lpb, const float* __restrict__ lgb,
      const float* __restrict__ rpb, const float* __restrict__ rgb,
      const float* __restrict__ ogb)
{
    extern __shared__ char smraw[];
    char* smb = (char*)(((uintptr_t)smraw + 1023) & ~(uintptr_t)1023);
    const uint32_t sb = smem_u32(smb);
    float*    pstage = (float*)(smb + 32768);
    uint32_t* st     = (uint32_t*)(smb + 32768);
    __shared__ float mask_s[64];
    __shared__ float pb_s[128], gb_s[128];

    const int tid  = threadIdx.x;
    const int lane = tid & 31;
    const int wid  = tid >> 5;
    const int wm   = wid & 1;
    const int wn   = wid >> 1;
    const int row0 = blockIdx.x * 64;
    const int i_idx = row0 >> 9;
    const int k0    = row0 & 511;

    // ---- load pair fp32 (coalesced) ----
    for (int idx = tid; idx < 64*32; idx += 256)
        ((float4*)pstage)[idx] = *(const float4*)&pair[(size_t)row0*DDIM + (idx << 2)];
    if (tid < 64) mask_s[tid] = mask[row0 + tid];
    __syncthreads();

    // ---- LN (4 threads/row) -> split bf16 A, swizzled ----
    {
        int row = tid >> 2, q = tid & 3;
        const float* pr = pstage + row*128 + q*32;
        float s = 0.f, ss = 0.f;
        #pragma unroll
        for (int t = 0; t < 8; t++){
            float4 v = *(const float4*)&pr[t*4];
            s  += v.x + v.y + v.z + v.w;
            ss += v.x*v.x + v.y*v.y + v.z*v.z + v.w*v.w;
        }
        s  += __shfl_xor_sync(0xFFFFFFFFu, s, 1);
        ss += __shfl_xor_sync(0xFFFFFFFFu, ss, 1);
        s  += __shfl_xor_sync(0xFFFFFFFFu, s, 2);
        ss += __shfl_xor_sync(0xFFFFFFFFu, ss, 2);
        float m  = s * (1.f/128.f);
        float vv = fmaxf(ss * (1.f/128.f) - m*m, 0.f);
        float iv = rsqrtf(vv + 1e-5f);
        #pragma unroll
        for (int cc = 0; cc < 4; cc++){
            int c = q*4 + cc;
            int e = c*8;
            uint4 hv, lv;
            unsigned short* hp = (unsigned short*)&hv;
            unsigned short* lp = (unsigned short*)&lv;
            #pragma unroll
            for (int t = 0; t < 8; t++){
                float y = (pstage[row*128 + e + t] - m)*iv*nw[e + t] + nb[e + t];
                uint32_t pk = split_pack(y);
                hp[t] = (unsigned short)(pk & 0xFFFFu);
                lp[t] = (unsigned short)(pk >> 16);
            }
            uint32_t off = (uint32_t)(row*256 + (((c ^ (row & 7)) << 4)));
            *(uint4*)(smb + off)         = hv;
            *(uint4*)(smb + 16384 + off) = lv;
        }
    }
    __syncthreads();

    auto loadW = [&](const __nv_bfloat16* srcH, const __nv_bfloat16* srcL){
        #pragma unroll
        for (int t = 0; t < 8; t++){
            int idx = tid + (t << 8);          // 0..2047 16B chunks
            int d = idx >> 4;
            int c = idx & 15;
            uint32_t off = (uint32_t)(d*256 + (((c ^ (d & 7)) << 4)));
            CP_ASYNC16(sb + 32768 + off, (const char*)srcH + (idx << 4));
            CP_ASYNC16(sb + 65536 + off, (const char*)srcL + (idx << 4));
        }
        CP_COMMIT();
    };

    // GEMM vs W in slots (hi@32K, lo@64K), A in [0,32K). acc[2][4][4].
    auto gemmW = [&](float (&acc)[2][4][4]){
        #pragma unroll
        for (int a = 0; a < 2; a++)
            #pragma unroll
            for (int b = 0; b < 4; b++)
                #pragma unroll
                for (int q = 0; q < 4; q++) acc[a][b][q] = 0.f;
        #pragma unroll 1
        for (int kk = 0; kk < 8; kk++){
            uint32_t ah[2][4], al[2][4];
            #pragma unroll
            for (int mt = 0; mt < 2; mt++){
                int r = wm*32 + mt*16 + (lane & 15);
                int c = kk*2 + (lane >> 4);
                uint32_t off = (uint32_t)(r*256 + (((c ^ (r & 7)) << 4)));
                ldsm4(ah[mt], sb + off);
                ldsm4(al[mt], sb + 16384 + off);
            }
            uint32_t bh[4][2], bl[4][2];
            #pragma unroll
            for (int nt = 0; nt < 4; nt++){
                int l = lane & 15;
                int n = wn*32 + nt*8 + (l & 7);
                int c = kk*2 + (l >> 3);
                uint32_t off = (uint32_t)(n*256 + (((c ^ (n & 7)) << 4)));
                ldsm2(bh[nt], sb + 32768 + off);
                ldsm2(bl[nt], sb + 65536 + off);
            }
            #pragma unroll
            for (int mt = 0; mt < 2; mt++)
                #pragma unroll
                for (int nt = 0; nt < 4; nt++){
                    mma_bf16(acc[mt][nt], ah[mt], bh[nt]);
                    mma_bf16(acc[mt][nt], ah[mt], bl[nt]);
                    mma_bf16(acc[mt][nt], al[mt], bh[nt]);
                }
        }
    };

    // ---- passes A (left) / B (right) ----
    #pragma unroll 1
    for (int pa = 0; pa < 2; pa++){
        loadW(g_wh + (pa*2)*16384, g_wl + (pa*2)*16384);
        if (tid < 128){
            pb_s[tid] = pa ? rpb[tid] : lpb[tid];
            gb_s[tid] = pa ? rgb[tid] : lgb[tid];
        }
        CP_WAIT0();
        __syncthreads();
        float accp[2][4][4];
        gemmW(accp);
        __syncthreads();

        loadW(g_wh + (pa*2+1)*16384, g_wl + (pa*2+1)*16384);
        CP_WAIT0();
        __syncthreads();
        float accg[2][4][4];
        gemmW(accg);
        __syncthreads();

        // epilogue -> packed st[m][n]
        #pragma unroll
        for (int mt = 0; mt < 2; mt++)
            #pragma unroll
            for (int nt = 0; nt < 4; nt++)
                #pragma unroll
                for (int q = 0; q < 4; q++){
                    int m = wm*32 + mt*16 + (lane >> 2) + ((q >> 1) << 3);
                    int n = wn*32 + nt*8 + ((lane & 3) << 1) + (q & 1);
                    float x = accp[mt][nt][q] + pb_s[n];
                    float g = accg[mt][nt][q] + gb_s[n];
                    st[m*129 + n] = split_pack(x * sigf(g) * mask_s[m]);
                }
        __syncthreads();

        // transpose write: [d][i][k]
        {
            __nv_bfloat16* ghi = pa ? g_rT_hi : g_lT_hi;
            __nv_bfloat16* glo = pa ? g_rT_lo : g_lT_lo;
            int dd = tid >> 1, half = tid & 1;
            uint4 oh[4], ol[4];
            unsigned short* hp = (unsigned short*)oh;
            unsigned short* lp = (unsigned short*)ol;
            #pragma unroll
            for (int kk = 0; kk < 32; kk++){
                uint32_t pk = st[(half*32 + kk)*129 + dd];
                hp[kk] = (unsigned short)(pk & 0xFFFFu);
                lp[kk] = (unsigned short)(pk >> 16);
            }
            size_t gb = ((size_t)dd*NDIM + i_idx)*NDIM + k0 + half*32;
            #pragma unroll
            for (int q = 0; q < 4; q++){
                *(uint4*)&ghi[gb + q*8] = oh[q];
                *(uint4*)&glo[gb + q*8] = ol[q];
            }
        }
        __syncthreads();
    }

    // ---- pass C: output gate (direct stores) ----
    loadW(g_wh + 4*16384, g_wl + 4*16384);
    if (tid < 128) pb_s[tid] = ogb[tid];
    CP_WAIT0();
    __syncthreads();
    {
        float acc[2][4][4];
        gemmW(acc);
        #pragma unroll
        for (int mt = 0; mt < 2; mt++)
            #pragma unroll
            for (int nt = 0; nt < 4; nt++)
                #pragma unroll
                for (int qq = 0; qq < 2; qq++){
                    int m = wm*32 + mt*16 + (lane >> 2) + qq*8;
                    int n = wn*32 + nt*8 + ((lane & 3) << 1);
                    float2 o;
                    o.x = sigf(acc[mt][nt][qq*2+0] + pb_s[n+0]);
                    o.y = sigf(acc[mt][nt][qq*2+1] + pb_s[n+1]);
                    *(float2*)&g_gate[(size_t)(row0 + m)*DDIM + n] = o;
                }
    }
}

// ================= Kernel 2: einsum, 512 threads (16 warps), 128x128xK64 =================
#define K2_BUF 65536

__global__ void __launch_bounds__(512, 1)
k2_mma()
{
    extern __shared__ char smraw[];
    char* smb = (char*)(((uintptr_t)smraw + 127) & ~(uintptr_t)127);
    const uint32_t sb = smem_u32(smb);

    const int tid  = threadIdx.x;
    const int lane = tid & 31;
    const int wid  = tid >> 5;
    const int d    = blockIdx.y;
    const int i0   = (blockIdx.x >> 2) * 128;
    const int j0   = (blockIdx.x & 3) * 128;
    const int wm   = wid & 3;          // 4 m-groups of 32 rows
    const int wn   = wid >> 2;         // 4 n-groups of 32 cols

    auto load_chunk = [&](int kc, int b){
        #pragma unroll
        for (int t = 0; t < 8; t++){
            int idx  = tid + (t << 9);       // 0..4095
            int tile = idx >> 10;
            int r    = (idx >> 3) & 127;
            int c    = idx & 7;
            const __nv_bfloat16* src = (tile == 0) ? g_lT_hi :
                                       (tile == 1) ? g_lT_lo :
                                       (tile == 2) ? g_rT_hi : g_rT_lo;
            int rb = ((tile & 2) ? j0 : i0) + r;
            const void* gp = &src[((size_t)d*NDIM + rb)*NDIM + kc + (c << 3)];
            uint32_t dst = sb + (b << 16) + (tile << 14) + (r << 7) + (((c ^ (r & 7)) << 4));
            CP_ASYNC16(dst, gp);
        }
        CP_COMMIT();
    };

    float acc[2][4][4];
    #pragma unroll
    for (int a = 0; a < 2; a++)
        #pragma unroll
        for (int b = 0; b < 4; b++)
            #pragma unroll
            for (int q = 0; q < 4; q++) acc[a][b][q] = 0.f;

    load_chunk(0, 0);
    load_chunk(64, 1);

    #pragma unroll 1
    for (int t = 0; t < 8; t++){
        if (t == 7) asm volatile("cp.async.wait_group 0;" ::: "memory");
        else        asm volatile("cp.async.wait_group 1;" ::: "memory");
        __syncthreads();

        const uint32_t base = sb + ((t & 1) << 16);
        #pragma unroll
        for (int kk = 0; kk < 4; kk++){
            uint32_t ah[2][4], al[2][4], bh[4][2], bl[4][2];
            #pragma unroll
            for (int mt = 0; mt < 2; mt++){
                int m = wm*32 + mt*16 + (lane & 15);
                int c = kk*2 + (lane >> 4);
                uint32_t off = (uint32_t)((m << 7) + (((c ^ (m & 7)) << 4)));
                ldsm4(ah[mt], base + off);
                ldsm4(al[mt], base + 16384 + off);
            }
            #pragma unroll
            for (int nt = 0; nt < 4; nt++){
                int l = lane & 15;
                int n = wn*32 + nt*8 + (l & 7);
                int c = kk*2 + (l >> 3);
                uint32_t off = (uint32_t)((n << 7) + (((c ^ (n & 7)) << 4)));
                ldsm2(bh[nt], base + 32768 + off);
                ldsm2(bl[nt], base + 49152 + off);
            }
            #pragma unroll
            for (int mt = 0; mt < 2; mt++)
                #pragma unroll
                for (int nt = 0; nt < 4; nt++){
                    mma_bf16(acc[mt][nt], ah[mt], bh[nt]);
                    mma_bf16(acc[mt][nt], ah[mt], bl[nt]);
                    mma_bf16(acc[mt][nt], al[mt], bh[nt]);
                }
        }
        __syncthreads();
        if (t + 2 < 8) load_chunk((t + 2)*64, t & 1);
    }

    #pragma unroll
    for (int mt = 0; mt < 2; mt++){
        int r0 = i0 + wm*32 + mt*16 + (lane >> 2);
        #pragma unroll
        for (int nt = 0; nt < 4; nt++){
            int c0 = j0 + wn*32 + nt*8 + (lane & 3)*2;
            float* p0 = &g_accT[((size_t)d*NDIM + r0)*NDIM + c0];
            float* p1 = &g_accT[((size_t)d*NDIM + r0 + 8)*NDIM + c0];
            p0[0] = acc[mt][nt][0]; p0[1] = acc[mt][nt][1];
            p1[0] = acc[mt][nt][2]; p1[1] = acc[mt][nt][3];
        }
    }
}

// ================= Kernel 3: LN(accT) @ opw.T + opb, times gate (64-j tiles, 2 CTA/SM) ====
// smem: A_hi [0,16K) A_lo [16K,32K) ; W hi [32K,64K) W lo [64K,96K); ts overlays [32K,66K)
__global__ void __launch_bounds__(256, 2)
k3_tc(const float* __restrict__ onw, const float* __restrict__ onb,
      const float* __restrict__ opb, float* __restrict__ out)
{
    extern __shared__ char smraw[];
    char* smb = (char*)(((uintptr_t)smraw + 1023) & ~(uintptr_t)1023);
    const uint32_t sb = smem_u32(smb);
    float* ts = (float*)(smb + 32768);          // [d][j] stride 66
    __shared__ float pb_s[128];
    __shared__ float sred[4][64], qred[4][64];
    __shared__ float mean_s[64], inv_s[64];

    const int tid  = threadIdx.x;
    const int lane = tid & 31;
    const int wid  = tid >> 5;
    const int wm   = wid & 1;
    const int wn   = wid >> 1;
    const int i_idx = blockIdx.x >> 3;
    const int j0    = (blockIdx.x & 7) * 64;
    const int row0  = i_idx*NDIM + j0;

    // load accT tile -> ts[d][j]
    for (int idx = tid; idx < 128*16; idx += 256){
        int d = idx >> 4, j4 = (idx & 15) << 2;
        float4 v = *(const float4*)&g_accT[(size_t)d*NN + row0 + j4];
        ts[d*66 + j4 + 0] = v.x;
        ts[d*66 + j4 + 1] = v.y;
        ts[d*66 + j4 + 2] = v.z;
        ts[d*66 + j4 + 3] = v.w;
    }
    if (tid < 128) pb_s[tid] = opb[tid];
    __syncthreads();

    // LN over d per j (4 thread-groups via warps; conflict-free j-major lanes)
    {
        int j = tid & 63, q = tid >> 6;
        float s = 0.f, ss = 0.f;
        #pragma unroll
        for (int t = 0; t < 32; t++){
            float v = ts[(q*32 + t)*66 + j];
            s += v; ss += v*v;
        }
        sred[q][j] = s; qred[q][j] = ss;
    }
    __syncthreads();
    if (tid < 64){
        int j = tid;
        float S  = sred[0][j] + sred[1][j] + sred[2][j] + sred[3][j];
        float SS = qred[0][j] + qred[1][j] + qred[2][j] + qred[3][j];
        float m  = S * (1.f/128.f);
        float vv = fmaxf(SS * (1.f/128.f) - m*m, 0.f);
        mean_s[j] = m;
        inv_s[j]  = rsqrtf(vv + 1e-5f);
    }
    __syncthreads();
    {
        int j = tid & 63, q = tid >> 6;
        float m = mean_s[j], iv = inv_s[j];
        #pragma unroll
        for (int cc = 0; cc < 4; cc++){
            int c = q*4 + cc;
            int e = c*8;
            uint4 hv, lv;
            unsigned short* hp = (unsigned short*)&hv;
            unsigned short* lp = (unsigned short*)&lv;
            #pragma unroll
            for (int t = 0; t < 8; t++){
                float y = (ts[(e + t)*66 + j] - m)*iv*onw[e + t] + onb[e + t];
                uint32_t pk = split_pack(y);
                hp[t] = (unsigned short)(pk & 0xFFFFu);
                lp[t] = (unsigned short)(pk >> 16);
            }
            uint32_t off = (uint32_t)(j*256 + (((c ^ (j & 7)) << 4)));
            *(uint4*)(smb + off)         = hv;
            *(uint4*)(smb + 16384 + off) = lv;
        }
    }
    __syncthreads();   // ts consumed

    // load opw hi/lo into W slots
    #pragma unroll
    for (int t = 0; t < 8; t++){
        int idx = tid + (t << 8);
        int d = idx >> 4;
        int c = idx & 15;
        uint32_t off = (uint32_t)(d*256 + (((c ^ (d & 7)) << 4)));
        CP_ASYNC16(sb + 32768 + off, (const char*)(g_wh + 5*16384) + (idx << 4));
        CP_ASYNC16(sb + 65536 + off, (const char*)(g_wl + 5*16384) + (idx << 4));
    }
    CP_COMMIT();
    CP_WAIT0();
    __syncthreads();

    float acc[2][4][4];
    #pragma unroll
    for (int a = 0; a < 2; a++)
        #pragma unroll
        for (int b = 0; b < 4; b++)
            #pragma unroll
            for (int q = 0; q < 4; q++) acc[a][b][q] = 0.f;

    #pragma unroll 1
    for (int kk = 0; kk < 8; kk++){
        uint32_t ah[2][4], al[2][4];
        #pragma unroll
        for (int mt = 0; mt < 2; mt++){
            int r = wm*32 + mt*16 + (lane & 15);
            int c = kk*2 + (lane >> 4);
            uint32_t off = (uint32_t)(r*256 + (((c ^ (r & 7)) << 4)));
            ldsm4(ah[mt], sb + off);
            ldsm4(al[mt], sb + 16384 + off);
        }
        uint32_t bh[4][2], bl[4][2];
        #pragma unroll
        for (int nt = 0; nt < 4; nt++){
            int l = lane & 15;
            int n = wn*32 + nt*8 + (l & 7);
            int c = kk*2 + (l >> 3);
            uint32_t off = (uint32_t)(n*256 + (((c ^ (n & 7)) << 4)));
            ldsm2(bh[nt], sb + 32768 + off);
            ldsm2(bl[nt], sb + 65536 + off);
        }
        #pragma unroll
        for (int mt = 0; mt < 2; mt++)
            #pragma unroll
            for (int nt = 0; nt < 4; nt++){
                mma_bf16(acc[mt][nt], ah[mt], bh[nt]);
                mma_bf16(acc[mt][nt], ah[mt], bl[nt]);
                mma_bf16(acc[mt][nt], al[mt], bh[nt]);
            }
    }

    // epilogue: (acc + opb) * gate, direct global loads/stores
    #pragma unroll
    for (int mt = 0; mt < 2; mt++)
        #pragma unroll
        for (int nt = 0; nt < 4; nt++)
            #pragma unroll
            for (int qq = 0; qq < 2; qq++){
                int j = wm*32 + mt*16 + (lane >> 2) + qq*8;
                int n = wn*32 + nt*8 + ((lane & 3) << 1);
                size_t base = (size_t)(row0 + j)*DDIM + n;
                float2 g2 = *(const float2*)&g_gate[base];
                float2 o;
                o.x = (acc[mt][nt][qq*2+0] + pb_s[n+0]) * g2.x;
                o.y = (acc[mt][nt][qq*2+1] + pb_s[n+1]) * g2.y;
                *(float2*)&out[base] = o;
            }
}

extern "C" void kernel_launch(void* const* d_in, const int* in_sizes, int n_in,
                              void* d_out, int out_size)
{
    const float* pair = (const float*)d_in[0];
    const float* mask = (const float*)d_in[1];
    const float* nw   = (const float*)d_in[2];
    const float* nb   = (const float*)d_in[3];
    const float* lpw  = (const float*)d_in[4];
    const float* lpb  = (const float*)d_in[5];
    const float* lgw  = (const float*)d_in[6];
    const float* lgb  = (const float*)d_in[7];
    const float* rpw  = (const float*)d_in[8];
    const float* rpb  = (const float*)d_in[9];
    const float* rgw  = (const float*)d_in[10];
    const float* rgb  = (const float*)d_in[11];
    const float* onw  = (const float*)d_in[12];
    const float* onb  = (const float*)d_in[13];
    const float* opw  = (const float*)d_in[14];
    const float* opb  = (const float*)d_in[15];
    const float* ogw  = (const float*)d_in[16];
    const float* ogb  = (const float*)d_in[17];
    float* out = (float*)d_out;

    const int smem1 = 98304 + 1024;
    const int smem2 = 2*K2_BUF + 256;
    const int smem3 = 98304 + 1024;
    cudaFuncSetAttribute(k1_tc,  cudaFuncAttributeMaxDynamicSharedMemorySize, smem1);
    cudaFuncSetAttribute(k2_mma, cudaFuncAttributeMaxDynamicSharedMemorySize, smem2);
    cudaFuncSetAttribute(k3_tc,  cudaFuncAttributeMaxDynamicSharedMemorySize, smem3);

    k0_prep<<<dim3(64, 6), 256>>>(lpw, lgw, rpw, rgw, ogw, opw);

    k1_tc<<<NN/64, 256, smem1>>>(pair, mask, nw, nb, lpb, lgb, rpb, rgb, ogb);

    dim3 g2(16, 128);
    k2_mma<<<g2, 512, smem2>>>();

    k3_tc<<<NN/64, 256, smem3>>>(onw, onb, opb, out);
}

// round 8
// speedup vs baseline: 3.8209x; 1.1758x over previous
#include <cuda_runtime.h>
#include <cuda_bf16.h>
#include <cstdint>

#define NDIM 512
#define DDIM 128
#define NN (NDIM*NDIM)

// ---------------- scratch (device globals; no allocation allowed) ----------------
__device__ __align__(256) __nv_bfloat16 g_lT_hi[(size_t)DDIM*NDIM*NDIM];
__device__ __align__(256) __nv_bfloat16 g_lT_lo[(size_t)DDIM*NDIM*NDIM];
__device__ __align__(256) __nv_bfloat16 g_rT_hi[(size_t)DDIM*NDIM*NDIM];
__device__ __align__(256) __nv_bfloat16 g_rT_lo[(size_t)DDIM*NDIM*NDIM];
__device__ __align__(256) float g_gate[(size_t)NN*DDIM];
__device__ __align__(256) float g_accT[(size_t)DDIM*NDIM*NDIM];   // [d][i][j]
// pre-split weights: 0=lp 1=lg 2=rp 3=rg 4=og 5=op
__device__ __align__(256) __nv_bfloat16 g_wh[6*16384];
__device__ __align__(256) __nv_bfloat16 g_wl[6*16384];

__device__ __forceinline__ float sigf(float x){ return 1.0f/(1.0f+__expf(-x)); }

__device__ __forceinline__ uint32_t split_pack(float v){
    __nv_bfloat16 h = __float2bfloat16(v);
    float hf = __bfloat162float(h);
    __nv_bfloat16 l = __float2bfloat16(v - hf);
    return (uint32_t)__bfloat16_as_ushort(h) | ((uint32_t)__bfloat16_as_ushort(l) << 16);
}

__device__ __forceinline__ uint32_t smem_u32(const void* p){
    uint32_t a;
    asm("{ .reg .u64 t; cvta.to.shared.u64 t, %1; cvt.u32.u64 %0, t; }" : "=r"(a) : "l"(p));
    return a;
}

// ---------------- baseline-PTX tensor-core helpers ----------------
__device__ __forceinline__ void ldsm4(uint32_t (&r)[4], uint32_t a){
    asm volatile("ldmatrix.sync.aligned.m8n8.x4.shared.b16 {%0,%1,%2,%3}, [%4];"
        : "=r"(r[0]), "=r"(r[1]), "=r"(r[2]), "=r"(r[3]) : "r"(a));
}
__device__ __forceinline__ void ldsm2(uint32_t (&r)[2], uint32_t a){
    asm volatile("ldmatrix.sync.aligned.m8n8.x2.shared.b16 {%0,%1}, [%2];"
        : "=r"(r[0]), "=r"(r[1]) : "r"(a));
}
__device__ __forceinline__ void mma_bf16(float (&c)[4], const uint32_t (&a)[4], const uint32_t (&b)[2]){
    asm volatile("mma.sync.aligned.m16n8k16.row.col.f32.bf16.bf16.f32 "
        "{%0,%1,%2,%3}, {%4,%5,%6,%7}, {%8,%9}, {%0,%1,%2,%3};"
        : "+f"(c[0]), "+f"(c[1]), "+f"(c[2]), "+f"(c[3])
        : "r"(a[0]), "r"(a[1]), "r"(a[2]), "r"(a[3]), "r"(b[0]), "r"(b[1]));
}
#define CP_ASYNC16(dst, src) \
    asm volatile("cp.async.cg.shared.global [%0], [%1], 16;" :: "r"(dst), "l"(src) : "memory")
#define CP_COMMIT() asm volatile("cp.async.commit_group;" ::: "memory")
#define CP_WAIT0()  asm volatile("cp.async.wait_group 0;" ::: "memory")

// ---------------- Kernel 0: pre-split weights to bf16 hi/lo ----------------
__global__ void k0_prep(const float* __restrict__ lpw, const float* __restrict__ lgw,
                        const float* __restrict__ rpw, const float* __restrict__ rgw,
                        const float* __restrict__ ogw, const float* __restrict__ opw)
{
    const float* srcs[6] = {lpw, lgw, rpw, rgw, ogw, opw};
    int m = blockIdx.y;
    int idx = blockIdx.x * 256 + threadIdx.x;
    float v = srcs[m][idx];
    __nv_bfloat16 h = __float2bfloat16(v);
    g_wh[m*16384 + idx] = h;
    g_wl[m*16384 + idx] = __float2bfloat16(v - __bfloat162float(h));
}

// ================= Kernel 1: LN + 5 gated projections (64-row tiles, 2 CTA/SM) ==========
// smem: A_hi [0,16K) A_lo [16K,32K) ; W hi [32K,64K) W lo [64K,96K)
//       st (packed epilogue staging) overlays the W region
__global__ void __launch_bounds__(256, 2)
k1_tc(const float* __restrict__ pair, const float* __restrict__ mask,
      const float* __restrict__ nw,  const float* __restrict__ nb,
      const float* __restrict__ lpb, const float* __restrict__ lgb,
      const float* __restrict__ rpb, const float* __restrict__ rgb,
      const float* __restrict__ ogb)
{
    extern __shared__ char smraw[];
    char* smb = (char*)(((uintptr_t)smraw + 1023) & ~(uintptr_t)1023);
    const uint32_t sb = smem_u32(smb);
    uint32_t* st = (uint32_t*)(smb + 32768);
    __shared__ float mask_s[64];
    __shared__ float pb_s[128], gb_s[128];

    const int tid  = threadIdx.x;
    const int lane = tid & 31;
    const int wid  = tid >> 5;
    const int wm   = wid & 1;
    const int wn   = wid >> 1;
    const int row0 = blockIdx.x * 64;
    const int i_idx = row0 >> 9;
    const int k0    = row0 & 511;

    auto loadW = [&](const __nv_bfloat16* srcH, const __nv_bfloat16* srcL){
        #pragma unroll
        for (int t = 0; t < 8; t++){
            int idx = tid + (t << 8);          // 0..2047 16B chunks
            int d = idx >> 4;
            int c = idx & 15;
            uint32_t off = (uint32_t)(d*256 + (((c ^ (d & 7)) << 4)));
            CP_ASYNC16(sb + 32768 + off, (const char*)srcH + (idx << 4));
            CP_ASYNC16(sb + 65536 + off, (const char*)srcL + (idx << 4));
        }
        CP_COMMIT();
    };

    // prefetch first weight pair (lp) — overlapped with LN below
    loadW(g_wh, g_wl);
    if (tid < 64) mask_s[tid] = mask[row0 + tid];

    // ---- LN from registers (4 threads per row), write split-bf16 A swizzled ----
    {
        int row = tid >> 2, q = tid & 3;
        const float4* pr = (const float4*)(pair + (size_t)(row0 + row)*128 + q*32);
        float v[32];
        float s = 0.f, ss = 0.f;
        #pragma unroll
        for (int t = 0; t < 8; t++){
            float4 x = pr[t];
            v[t*4+0] = x.x; v[t*4+1] = x.y; v[t*4+2] = x.z; v[t*4+3] = x.w;
            s  += x.x + x.y + x.z + x.w;
            ss += x.x*x.x + x.y*x.y + x.z*x.z + x.w*x.w;
        }
        s  += __shfl_xor_sync(0xFFFFFFFFu, s, 1);
        ss += __shfl_xor_sync(0xFFFFFFFFu, ss, 1);
        s  += __shfl_xor_sync(0xFFFFFFFFu, s, 2);
        ss += __shfl_xor_sync(0xFFFFFFFFu, ss, 2);
        float m  = s * (1.f/128.f);
        float vv = fmaxf(ss * (1.f/128.f) - m*m, 0.f);
        float iv = rsqrtf(vv + 1e-5f);
        #pragma unroll
        for (int cc = 0; cc < 4; cc++){
            int c = q*4 + cc;
            int e = c*8;
            uint4 hv, lv;
            unsigned short* hp = (unsigned short*)&hv;
            unsigned short* lp = (unsigned short*)&lv;
            #pragma unroll
            for (int t = 0; t < 8; t++){
                float y = (v[cc*8 + t] - m)*iv*nw[e + t] + nb[e + t];
                uint32_t pk = split_pack(y);
                hp[t] = (unsigned short)(pk & 0xFFFFu);
                lp[t] = (unsigned short)(pk >> 16);
            }
            uint32_t off = (uint32_t)(row*256 + (((c ^ (row & 7)) << 4)));
            *(uint4*)(smb + off)         = hv;
            *(uint4*)(smb + 16384 + off) = lv;
        }
    }

    // GEMM vs W in slots (hi@32K, lo@64K), A in [0,32K)
    auto gemmW = [&](float (&acc)[2][4][4]){
        #pragma unroll
        for (int a = 0; a < 2; a++)
            #pragma unroll
            for (int b = 0; b < 4; b++)
                #pragma unroll
                for (int q = 0; q < 4; q++) acc[a][b][q] = 0.f;
        #pragma unroll 1
        for (int kk = 0; kk < 8; kk++){
            uint32_t ah[2][4], al[2][4];
            #pragma unroll
            for (int mt = 0; mt < 2; mt++){
                int r = wm*32 + mt*16 + (lane & 15);
                int c = kk*2 + (lane >> 4);
                uint32_t off = (uint32_t)(r*256 + (((c ^ (r & 7)) << 4)));
                ldsm4(ah[mt], sb + off);
                ldsm4(al[mt], sb + 16384 + off);
            }
            uint32_t bh[4][2], bl[4][2];
            #pragma unroll
            for (int nt = 0; nt < 4; nt++){
                int l = lane & 15;
                int n = wn*32 + nt*8 + (l & 7);
                int c = kk*2 + (l >> 3);
                uint32_t off = (uint32_t)(n*256 + (((c ^ (n & 7)) << 4)));
                ldsm2(bh[nt], sb + 32768 + off);
                ldsm2(bl[nt], sb + 65536 + off);
            }
            #pragma unroll
            for (int mt = 0; mt < 2; mt++)
                #pragma unroll
                for (int nt = 0; nt < 4; nt++){
                    mma_bf16(acc[mt][nt], ah[mt], bh[nt]);
                    mma_bf16(acc[mt][nt], ah[mt], bl[nt]);
                    mma_bf16(acc[mt][nt], al[mt], bh[nt]);
                }
        }
    };

    // ---- passes A (left) / B (right) ----
    #pragma unroll 1
    for (int pa = 0; pa < 2; pa++){
        if (pa) loadW(g_wh + 2*16384, g_wl + 2*16384);   // rp (pass A's lp was prefetched)
        if (tid < 128){
            pb_s[tid] = pa ? rpb[tid] : lpb[tid];
            gb_s[tid] = pa ? rgb[tid] : lgb[tid];
        }
        CP_WAIT0();
        __syncthreads();
        float accp[2][4][4];
        gemmW(accp);
        __syncthreads();

        loadW(g_wh + (pa*2+1)*16384, g_wl + (pa*2+1)*16384);
        CP_WAIT0();
        __syncthreads();
        float accg[2][4][4];
        gemmW(accg);
        __syncthreads();

        // epilogue -> packed st[m][n]
        #pragma unroll
        for (int mt = 0; mt < 2; mt++)
            #pragma unroll
            for (int nt = 0; nt < 4; nt++)
                #pragma unroll
                for (int q = 0; q < 4; q++){
                    int m = wm*32 + mt*16 + (lane >> 2) + ((q >> 1) << 3);
                    int n = wn*32 + nt*8 + ((lane & 3) << 1) + (q & 1);
                    float x = accp[mt][nt][q] + pb_s[n];
                    float g = accg[mt][nt][q] + gb_s[n];
                    st[m*129 + n] = split_pack(x * sigf(g) * mask_s[m]);
                }
        __syncthreads();

        // transpose write: [d][i][k]
        {
            __nv_bfloat16* ghi = pa ? g_rT_hi : g_lT_hi;
            __nv_bfloat16* glo = pa ? g_rT_lo : g_lT_lo;
            int dd = tid >> 1, half = tid & 1;
            uint4 oh[4], ol[4];
            unsigned short* hp = (unsigned short*)oh;
            unsigned short* lp = (unsigned short*)ol;
            #pragma unroll
            for (int kk = 0; kk < 32; kk++){
                uint32_t pk = st[(half*32 + kk)*129 + dd];
                hp[kk] = (unsigned short)(pk & 0xFFFFu);
                lp[kk] = (unsigned short)(pk >> 16);
            }
            size_t gb = ((size_t)dd*NDIM + i_idx)*NDIM + k0 + half*32;
            #pragma unroll
            for (int q = 0; q < 4; q++){
                *(uint4*)&ghi[gb + q*8] = oh[q];
                *(uint4*)&glo[gb + q*8] = ol[q];
            }
        }
        __syncthreads();
    }

    // ---- pass C: output gate (direct stores) ----
    loadW(g_wh + 4*16384, g_wl + 4*16384);
    if (tid < 128) pb_s[tid] = ogb[tid];
    CP_WAIT0();
    __syncthreads();
    {
        float acc[2][4][4];
        gemmW(acc);
        #pragma unroll
        for (int mt = 0; mt < 2; mt++)
            #pragma unroll
            for (int nt = 0; nt < 4; nt++)
                #pragma unroll
                for (int qq = 0; qq < 2; qq++){
                    int m = wm*32 + mt*16 + (lane >> 2) + qq*8;
                    int n = wn*32 + nt*8 + ((lane & 3) << 1);
                    float2 o;
                    o.x = sigf(acc[mt][nt][qq*2+0] + pb_s[n+0]);
                    o.y = sigf(acc[mt][nt][qq*2+1] + pb_s[n+1]);
                    *(float2*)&g_gate[(size_t)(row0 + m)*DDIM + n] = o;
                }
    }
}

// ================= Kernel 2: einsum, 128x64 tiles, 2 CTA/SM =================
// smem per buffer (48KB): A_hi[0,16K) A_lo[16K,32K) B_hi[32K,40K) B_lo[40K,48K)
#define K2_BUF 49152

__global__ void __launch_bounds__(256, 2)
k2_mma()
{
    extern __shared__ char smraw[];
    char* smb = (char*)(((uintptr_t)smraw + 127) & ~(uintptr_t)127);
    const uint32_t sb = smem_u32(smb);

    const int tid  = threadIdx.x;
    const int lane = tid & 31;
    const int wid  = tid >> 5;
    const int d    = blockIdx.y;
    const int i0   = (blockIdx.x >> 3) * 128;
    const int j0   = (blockIdx.x & 7) * 64;
    const int wm   = wid & 3;          // 4 m-groups of 32 rows
    const int wn   = wid >> 2;         // 2 n-groups of 32 cols

    auto load_chunk = [&](int kc, int b){
        #pragma unroll
        for (int t = 0; t < 12; t++){
            int idx = tid + (t << 8);          // 0..3071 16B chunks
            const __nv_bfloat16* src;
            int rb, r;
            uint32_t roff;
            if (idx < 2048){
                src = (idx & 1024) ? g_lT_lo : g_lT_hi;
                rb = i0; r = (idx >> 3) & 127;
                roff = (idx & 1024) ? 16384u : 0u;
            } else {
                int x = idx - 2048;
                src = (x & 512) ? g_rT_lo : g_rT_hi;
                rb = j0; r = (x >> 3) & 63;
                roff = (x & 512) ? 40960u : 32768u;
            }
            int c = idx & 7;
            const void* gp = &src[((size_t)d*NDIM + rb + r)*NDIM + kc + (c << 3)];
            uint32_t dst = sb + b*K2_BUF + roff + (r << 7) + (((c ^ (r & 7)) << 4));
            CP_ASYNC16(dst, gp);
        }
        CP_COMMIT();
    };

    float acc[2][4][4];
    #pragma unroll
    for (int a = 0; a < 2; a++)
        #pragma unroll
        for (int b = 0; b < 4; b++)
            #pragma unroll
            for (int q = 0; q < 4; q++) acc[a][b][q] = 0.f;

    load_chunk(0, 0);
    load_chunk(64, 1);

    #pragma unroll 1
    for (int t = 0; t < 8; t++){
        if (t == 7) asm volatile("cp.async.wait_group 0;" ::: "memory");
        else        asm volatile("cp.async.wait_group 1;" ::: "memory");
        __syncthreads();

        const uint32_t base = sb + (t & 1)*K2_BUF;
        #pragma unroll
        for (int kk = 0; kk < 4; kk++){
            uint32_t ah[2][4], al[2][4], bh[4][2], bl[4][2];
            #pragma unroll
            for (int mt = 0; mt < 2; mt++){
                int m = wm*32 + mt*16 + (lane & 15);
                int c = kk*2 + (lane >> 4);
                uint32_t off = (uint32_t)((m << 7) + (((c ^ (m & 7)) << 4)));
                ldsm4(ah[mt], base + off);
                ldsm4(al[mt], base + 16384 + off);
            }
            #pragma unroll
            for (int nt = 0; nt < 4; nt++){
                int l = lane & 15;
                int n = wn*32 + nt*8 + (l & 7);
                int c = kk*2 + (l >> 3);
                uint32_t off = (uint32_t)((n << 7) + (((c ^ (n & 7)) << 4)));
                ldsm2(bh[nt], base + 32768 + off);
                ldsm2(bl[nt], base + 40960 + off);
            }
            #pragma unroll
            for (int mt = 0; mt < 2; mt++)
                #pragma unroll
                for (int nt = 0; nt < 4; nt++){
                    mma_bf16(acc[mt][nt], ah[mt], bh[nt]);
                    mma_bf16(acc[mt][nt], ah[mt], bl[nt]);
                    mma_bf16(acc[mt][nt], al[mt], bh[nt]);
                }
        }
        __syncthreads();
        if (t + 2 < 8) load_chunk((t + 2)*64, t & 1);
    }

    #pragma unroll
    for (int mt = 0; mt < 2; mt++){
        int r0 = i0 + wm*32 + mt*16 + (lane >> 2);
        #pragma unroll
        for (int nt = 0; nt < 4; nt++){
            int c0 = j0 + wn*32 + nt*8 + (lane & 3)*2;
            float* p0 = &g_accT[((size_t)d*NDIM + r0)*NDIM + c0];
            float* p1 = &g_accT[((size_t)d*NDIM + r0 + 8)*NDIM + c0];
            p0[0] = acc[mt][nt][0]; p0[1] = acc[mt][nt][1];
            p1[0] = acc[mt][nt][2]; p1[1] = acc[mt][nt][3];
        }
    }
}

// ================= Kernel 3: LN(accT) @ opw.T + opb, times gate (64-j tiles, 2 CTA/SM) ====
// smem: A_hi [0,16K) A_lo [16K,32K) ; W hi [32K,64K) W lo [64K,96K) (prefetched at t=0)
__global__ void __launch_bounds__(256, 2)
k3_tc(const float* __restrict__ onw, const float* __restrict__ onb,
      const float* __restrict__ opb, float* __restrict__ out)
{
    extern __shared__ char smraw[];
    char* smb = (char*)(((uintptr_t)smraw + 1023) & ~(uintptr_t)1023);
    const uint32_t sb = smem_u32(smb);
    __shared__ float pb_s[128];
    __shared__ float sred[4][64], qred[4][64];
    __shared__ float mean_s[64], inv_s[64];

    const int tid  = threadIdx.x;
    const int lane = tid & 31;
    const int wid  = tid >> 5;
    const int wm   = wid & 1;
    const int wn   = wid >> 1;
    const int i_idx = blockIdx.x >> 3;
    const int j0    = (blockIdx.x & 7) * 64;
    const int row0  = i_idx*NDIM + j0;

    // prefetch opw hi/lo into W slots — overlaps with everything below
    #pragma unroll
    for (int t = 0; t < 8; t++){
        int idx = tid + (t << 8);
        int d = idx >> 4;
        int c = idx & 15;
        uint32_t off = (uint32_t)(d*256 + (((c ^ (d & 7)) << 4)));
        CP_ASYNC16(sb + 32768 + off, (const char*)(g_wh + 5*16384) + (idx << 4));
        CP_ASYNC16(sb + 65536 + off, (const char*)(g_wl + 5*16384) + (idx << 4));
    }
    CP_COMMIT();
    if (tid < 128) pb_s[tid] = opb[tid];

    // ---- LN over d per j, operands in registers ----
    const int jj = tid & 63, qq4 = tid >> 6;
    float v[32];
    {
        const float* gp = g_accT + (size_t)(qq4*32)*NN + row0 + jj;
        float s = 0.f, ss = 0.f;
        #pragma unroll
        for (int t = 0; t < 32; t++){
            float x = gp[(size_t)t*NN];
            v[t] = x;
            s += x; ss += x*x;
        }
        sred[qq4][jj] = s; qred[qq4][jj] = ss;
    }
    __syncthreads();
    if (tid < 64){
        int j = tid;
        float S  = sred[0][j] + sred[1][j] + sred[2][j] + sred[3][j];
        float SS = qred[0][j] + qred[1][j] + qred[2][j] + qred[3][j];
        float m  = S * (1.f/128.f);
        float vv = fmaxf(SS * (1.f/128.f) - m*m, 0.f);
        mean_s[j] = m;
        inv_s[j]  = rsqrtf(vv + 1e-5f);
    }
    __syncthreads();
    {
        float m = mean_s[jj], iv = inv_s[jj];
        #pragma unroll
        for (int cc = 0; cc < 4; cc++){
            int c = qq4*4 + cc;
            int e = c*8;
            uint4 hv, lv;
            unsigned short* hp = (unsigned short*)&hv;
            unsigned short* lp = (unsigned short*)&lv;
            #pragma unroll
            for (int t = 0; t < 8; t++){
                float y = (v[cc*8 + t] - m)*iv*onw[e + t] + onb[e + t];
                uint32_t pk = split_pack(y);
                hp[t] = (unsigned short)(pk & 0xFFFFu);
                lp[t] = (unsigned short)(pk >> 16);
            }
            uint32_t off = (uint32_t)(jj*256 + (((c ^ (jj & 7)) << 4)));
            *(uint4*)(smb + off)         = hv;
            *(uint4*)(smb + 16384 + off) = lv;
        }
    }
    CP_WAIT0();
    __syncthreads();

    float acc[2][4][4];
    #pragma unroll
    for (int a = 0; a < 2; a++)
        #pragma unroll
        for (int b = 0; b < 4; b++)
            #pragma unroll
            for (int q = 0; q < 4; q++) acc[a][b][q] = 0.f;

    #pragma unroll 1
    for (int kk = 0; kk < 8; kk++){
        uint32_t ah[2][4], al[2][4];
        #pragma unroll
        for (int mt = 0; mt < 2; mt++){
            int r = wm*32 + mt*16 + (lane & 15);
            int c = kk*2 + (lane >> 4);
            uint32_t off = (uint32_t)(r*256 + (((c ^ (r & 7)) << 4)));
            ldsm4(ah[mt], sb + off);
            ldsm4(al[mt], sb + 16384 + off);
        }
        uint32_t bh[4][2], bl[4][2];
        #pragma unroll
        for (int nt = 0; nt < 4; nt++){
            int l = lane & 15;
            int n = wn*32 + nt*8 + (l & 7);
            int c = kk*2 + (l >> 3);
            uint32_t off = (uint32_t)(n*256 + (((c ^ (n & 7)) << 4)));
            ldsm2(bh[nt], sb + 32768 + off);
            ldsm2(bl[nt], sb + 65536 + off);
        }
        #pragma unroll
        for (int mt = 0; mt < 2; mt++)
            #pragma unroll
            for (int nt = 0; nt < 4; nt++){
                mma_bf16(acc[mt][nt], ah[mt], bh[nt]);
                mma_bf16(acc[mt][nt], ah[mt], bl[nt]);
                mma_bf16(acc[mt][nt], al[mt], bh[nt]);
            }
    }

    // epilogue: (acc + opb) * gate, direct global loads/stores
    #pragma unroll
    for (int mt = 0; mt < 2; mt++)
        #pragma unroll
        for (int nt = 0; nt < 4; nt++)
            #pragma unroll
            for (int qq = 0; qq < 2; qq++){
                int j = wm*32 + mt*16 + (lane >> 2) + qq*8;
                int n = wn*32 + nt*8 + ((lane & 3) << 1);
                size_t base = (size_t)(row0 + j)*DDIM + n;
                float2 g2 = *(const float2*)&g_gate[base];
                float2 o;
                o.x = (acc[mt][nt][qq*2+0] + pb_s[n+0]) * g2.x;
                o.y = (acc[mt][nt][qq*2+1] + pb_s[n+1]) * g2.y;
                *(float2*)&out[base] = o;
            }
}

extern "C" void kernel_launch(void* const* d_in, const int* in_sizes, int n_in,
                              void* d_out, int out_size)
{
    const float* pair = (const float*)d_in[0];
    const float* mask = (const float*)d_in[1];
    const float* nw   = (const float*)d_in[2];
    const float* nb   = (const float*)d_in[3];
    const float* lpw  = (const float*)d_in[4];
    const float* lpb  = (const float*)d_in[5];
    const float* lgw  = (const float*)d_in[6];
    const float* lgb  = (const float*)d_in[7];
    const float* rpw  = (const float*)d_in[8];
    const float* rpb  = (const float*)d_in[9];
    const float* rgw  = (const float*)d_in[10];
    const float* rgb  = (const float*)d_in[11];
    const float* onw  = (const float*)d_in[12];
    const float* onb  = (const float*)d_in[13];
    const float* opw  = (const float*)d_in[14];
    const float* opb  = (const float*)d_in[15];
    const float* ogw  = (const float*)d_in[16];
    const float* ogb  = (const float*)d_in[17];
    float* out = (float*)d_out;

    const int smem1 = 98304 + 1024;
    const int smem2 = 2*K2_BUF + 256;
    const int smem3 = 98304 + 1024;
    cudaFuncSetAttribute(k1_tc,  cudaFuncAttributeMaxDynamicSharedMemorySize, smem1);
    cudaFuncSetAttribute(k2_mma, cudaFuncAttributeMaxDynamicSharedMemorySize, smem2);
    cudaFuncSetAttribute(k3_tc,  cudaFuncAttributeMaxDynamicSharedMemorySize, smem3);

    k0_prep<<<dim3(64, 6), 256>>>(lpw, lgw, rpw, rgw, ogw, opw);

    k1_tc<<<NN/64, 256, smem1>>>(pair, mask, nw, nb, lpb, lgb, rpb, rgb, ogb);

    dim3 g2(32, 128);   // x = i-tile(4) x j-tile(8): consecutive blocks share the A tile in L2
    k2_mma<<<g2, 256, smem2>>>();

    k3_tc<<<NN/64, 256, smem3>>>(onw, onb, opb, out);
}

// round 9
// speedup vs baseline: 4.2744x; 1.1187x over previous
#include <cuda_runtime.h>
#include <cuda_fp16.h>
#include <cstdint>

#define NDIM 512
#define DDIM 128
#define NN (NDIM*NDIM)

// ---------------- scratch (device globals; no allocation allowed) ----------------
// packed fp16 tensors: each uint32 = (lo16<<16)|hi16 along fake-k axis
__device__ __align__(256) uint32_t g_lP[(size_t)DDIM*NN];   // left, dup-packed
__device__ __align__(256) uint32_t g_rP[(size_t)DDIM*NN];   // right, split-packed
__device__ __align__(256) float g_gate[(size_t)NN*DDIM];
__device__ __align__(256) float g_accT[(size_t)DDIM*NN];    // [d][i][j]
// pre-packed weights (dup fp16): 0=lp 1=lg 2=rp 3=rg 4=og 5=op
__device__ __align__(256) uint32_t g_wp[6*16384];

__device__ __forceinline__ float sigf(float x){ return 1.0f/(1.0f+__expf(-x)); }

__device__ __forceinline__ uint32_t pk_split(float v){
    __half h = __float2half_rn(v);
    __half l = __float2half_rn(v - __half2float(h));
    return (uint32_t)__half_as_ushort(h) | ((uint32_t)__half_as_ushort(l) << 16);
}
__device__ __forceinline__ uint32_t pk_dup(float v){
    uint32_t h = (uint32_t)__half_as_ushort(__float2half_rn(v));
    return h | (h << 16);
}

__device__ __forceinline__ uint32_t smem_u32(const void* p){
    uint32_t a;
    asm("{ .reg .u64 t; cvta.to.shared.u64 t, %1; cvt.u32.u64 %0, t; }" : "=r"(a) : "l"(p));
    return a;
}

// ---------------- baseline-PTX tensor-core helpers (fp16) ----------------
__device__ __forceinline__ void ldsm4(uint32_t (&r)[4], uint32_t a){
    asm volatile("ldmatrix.sync.aligned.m8n8.x4.shared.b16 {%0,%1,%2,%3}, [%4];"
        : "=r"(r[0]), "=r"(r[1]), "=r"(r[2]), "=r"(r[3]) : "r"(a));
}
__device__ __forceinline__ void ldsm2(uint32_t (&r)[2], uint32_t a){
    asm volatile("ldmatrix.sync.aligned.m8n8.x2.shared.b16 {%0,%1}, [%2];"
        : "=r"(r[0]), "=r"(r[1]) : "r"(a));
}
__device__ __forceinline__ void mma_f16(float (&c)[4], const uint32_t (&a)[4], const uint32_t (&b)[2]){
    asm volatile("mma.sync.aligned.m16n8k16.row.col.f32.f16.f16.f32 "
        "{%0,%1,%2,%3}, {%4,%5,%6,%7}, {%8,%9}, {%0,%1,%2,%3};"
        : "+f"(c[0]), "+f"(c[1]), "+f"(c[2]), "+f"(c[3])
        : "r"(a[0]), "r"(a[1]), "r"(a[2]), "r"(a[3]), "r"(b[0]), "r"(b[1]));
}
#define CP_ASYNC16(dst, src) \
    asm volatile("cp.async.cg.shared.global [%0], [%1], 16;" :: "r"(dst), "l"(src) : "memory")
#define CP_COMMIT() asm volatile("cp.async.commit_group;" ::: "memory")
#define CP_WAIT0()  asm volatile("cp.async.wait_group 0;" ::: "memory")

// ---------------- Kernel 0: pre-pack weights (dup fp16) ----------------
__global__ void k0_prep(const float* __restrict__ lpw, const float* __restrict__ lgw,
                        const float* __restrict__ rpw, const float* __restrict__ rgw,
                        const float* __restrict__ ogw, const float* __restrict__ opw)
{
    const float* srcs[6] = {lpw, lgw, rpw, rgw, ogw, opw};
    int m = blockIdx.y;
    int idx = blockIdx.x * 256 + threadIdx.x;
    g_wp[m*16384 + idx] = pk_dup(srcs[m][idx]);
}

// ================= Kernel 1: LN + 5 gated projections (64-row tiles, 2 CTA/SM) ==========
// smem: A packed [0,32K) 64 rows x 512B ; W packed [32K,96K) 128 rows x 512B
//       st (uint32 staging) overlays the W region
__global__ void __launch_bounds__(256, 2)
k1_tc(const float* __restrict__ pair, const float* __restrict__ mask,
      const float* __restrict__ nw,  const float* __restrict__ nb,
      const float* __restrict__ lpb, const float* __restrict__ lgb,
      const float* __restrict__ rpb, const float* __restrict__ rgb,
      const float* __restrict__ ogb)
{
    extern __shared__ char smraw[];
    char* smb = (char*)(((uintptr_t)smraw + 1023) & ~(uintptr_t)1023);
    const uint32_t sb = smem_u32(smb);
    uint32_t* st = (uint32_t*)(smb + 32768);
    __shared__ float mask_s[64];
    __shared__ float pb_s[128], gb_s[128];

    const int tid  = threadIdx.x;
    const int lane = tid & 31;
    const int wid  = tid >> 5;
    const int wm   = wid & 1;
    const int wn   = wid >> 1;
    const int row0 = blockIdx.x * 64;
    const int i_idx = row0 >> 9;
    const int k0    = row0 & 511;

    auto loadW = [&](const uint32_t* src){
        #pragma unroll
        for (int t = 0; t < 16; t++){
            int idx = tid + (t << 8);          // 0..4095 16B chunks
            int d = idx >> 5;
            int c = idx & 31;
            uint32_t off = (uint32_t)(d*512 + (((c ^ (d & 7)) << 4)));
            CP_ASYNC16(sb + 32768 + off, (const char*)src + (idx << 4));
        }
        CP_COMMIT();
    };

    // prefetch first weight (lp) — overlapped with LN below
    loadW(g_wp);
    if (tid < 64) mask_s[tid] = mask[row0 + tid];

    // ---- LN from registers (4 threads per row), write packed-split A ----
    {
        int row = tid >> 2, q = tid & 3;
        const float4* pr = (const float4*)(pair + (size_t)(row0 + row)*128 + q*32);
        float v[32];
        float s = 0.f, ss = 0.f;
        #pragma unroll
        for (int t = 0; t < 8; t++){
            float4 x = pr[t];
            v[t*4+0] = x.x; v[t*4+1] = x.y; v[t*4+2] = x.z; v[t*4+3] = x.w;
            s  += x.x + x.y + x.z + x.w;
            ss += x.x*x.x + x.y*x.y + x.z*x.z + x.w*x.w;
        }
        s  += __shfl_xor_sync(0xFFFFFFFFu, s, 1);
        ss += __shfl_xor_sync(0xFFFFFFFFu, ss, 1);
        s  += __shfl_xor_sync(0xFFFFFFFFu, s, 2);
        ss += __shfl_xor_sync(0xFFFFFFFFu, ss, 2);
        float m  = s * (1.f/128.f);
        float vv = fmaxf(ss * (1.f/128.f) - m*m, 0.f);
        float iv = rsqrtf(vv + 1e-5f);
        #pragma unroll
        for (int cc = 0; cc < 8; cc++){
            int c = q*8 + cc;
            int e = q*32 + cc*4;
            uint4 pv;
            uint32_t* pp = (uint32_t*)&pv;
            #pragma unroll
            for (int t = 0; t < 4; t++){
                float y = (v[cc*4 + t] - m)*iv*nw[e + t] + nb[e + t];
                pp[t] = pk_split(y);
            }
            uint32_t off = (uint32_t)(row*512 + (((c ^ (row & 7)) << 4)));
            *(uint4*)(smb + off) = pv;
        }
    }

    // GEMM: A packed [0,32K), W packed [32K,96K). 1 MMA per (fkk,mt,nt).
    auto gemmW = [&](float (&acc)[2][4][4]){
        #pragma unroll
        for (int a = 0; a < 2; a++)
            #pragma unroll
            for (int b = 0; b < 4; b++)
                #pragma unroll
                for (int q = 0; q < 4; q++) acc[a][b][q] = 0.f;
        #pragma unroll 1
        for (int fkk = 0; fkk < 16; fkk++){
            uint32_t ap[2][4];
            #pragma unroll
            for (int mt = 0; mt < 2; mt++){
                int r = wm*32 + mt*16 + (lane & 15);
                int c = fkk*2 + (lane >> 4);
                ldsm4(ap[mt], sb + (uint32_t)(r*512 + (((c ^ (r & 7)) << 4))));
            }
            uint32_t bp[4][2];
            #pragma unroll
            for (int nt = 0; nt < 4; nt++){
                int l = lane & 15;
                int n = wn*32 + nt*8 + (l & 7);
                int c = fkk*2 + (l >> 3);
                ldsm2(bp[nt], sb + 32768 + (uint32_t)(n*512 + (((c ^ (n & 7)) << 4))));
            }
            #pragma unroll
            for (int mt = 0; mt < 2; mt++)
                #pragma unroll
                for (int nt = 0; nt < 4; nt++)
                    mma_f16(acc[mt][nt], ap[mt], bp[nt]);
        }
    };

    // ---- passes A (left, dup-packed out) / B (right, split-packed out) ----
    #pragma unroll 1
    for (int pa = 0; pa < 2; pa++){
        if (pa) loadW(g_wp + 2*16384);
        if (tid < 128){
            pb_s[tid] = pa ? rpb[tid] : lpb[tid];
            gb_s[tid] = pa ? rgb[tid] : lgb[tid];
        }
        CP_WAIT0();
        __syncthreads();
        float accp[2][4][4];
        gemmW(accp);
        __syncthreads();

        loadW(g_wp + (pa*2+1)*16384);
        CP_WAIT0();
        __syncthreads();
        float accg[2][4][4];
        gemmW(accg);
        __syncthreads();

        #pragma unroll
        for (int mt = 0; mt < 2; mt++)
            #pragma unroll
            for (int nt = 0; nt < 4; nt++)
                #pragma unroll
                for (int q = 0; q < 4; q++){
                    int m = wm*32 + mt*16 + (lane >> 2) + ((q >> 1) << 3);
                    int n = wn*32 + nt*8 + ((lane & 3) << 1) + (q & 1);
                    float x = accp[mt][nt][q] + pb_s[n];
                    float g = accg[mt][nt][q] + gb_s[n];
                    float y = x * sigf(g) * mask_s[m];
                    st[m*129 + n] = pa ? pk_split(y) : pk_dup(y);
                }
        __syncthreads();

        // transpose write: packed [d][i][k]
        {
            uint32_t* gP = pa ? g_rP : g_lP;
            int dd = tid >> 1, half = tid & 1;
            uint4 o[8];
            uint32_t* op = (uint32_t*)o;
            #pragma unroll
            for (int kk = 0; kk < 32; kk++)
                op[kk] = st[(half*32 + kk)*129 + dd];
            uint32_t* dst = gP + ((size_t)dd*NDIM + i_idx)*NDIM + k0 + half*32;
            #pragma unroll
            for (int q = 0; q < 8; q++)
                *(uint4*)(dst + q*4) = o[q];
        }
        __syncthreads();
    }

    // ---- pass C: output gate (direct stores) ----
    loadW(g_wp + 4*16384);
    if (tid < 128) pb_s[tid] = ogb[tid];
    CP_WAIT0();
    __syncthreads();
    {
        float acc[2][4][4];
        gemmW(acc);
        #pragma unroll
        for (int mt = 0; mt < 2; mt++)
            #pragma unroll
            for (int nt = 0; nt < 4; nt++)
                #pragma unroll
                for (int qq = 0; qq < 2; qq++){
                    int m = wm*32 + mt*16 + (lane >> 2) + qq*8;
                    int n = wn*32 + nt*8 + ((lane & 3) << 1);
                    float2 o;
                    o.x = sigf(acc[mt][nt][qq*2+0] + pb_s[n+0]);
                    o.y = sigf(acc[mt][nt][qq*2+1] + pb_s[n+1]);
                    *(float2*)&g_gate[(size_t)(row0 + m)*DDIM + n] = o;
                }
    }
}

// ================= Kernel 2: einsum, 128x64 tiles, K32 chunks, 3 CTA/SM =================
// per buffer (24KB): A packed [0,16K) 128x128B ; B packed [16K,24K) 64x128B
#define K2_BUF 24576

__global__ void __launch_bounds__(256, 3)
k2_mma()
{
    extern __shared__ char smraw[];
    char* smb = (char*)(((uintptr_t)smraw + 127) & ~(uintptr_t)127);
    const uint32_t sb = smem_u32(smb);

    const int tid  = threadIdx.x;
    const int lane = tid & 31;
    const int wid  = tid >> 5;
    const int d    = blockIdx.y;
    const int i0   = (blockIdx.x >> 3) * 128;
    const int j0   = (blockIdx.x & 7) * 64;
    const int wm   = wid & 3;          // 4 m-groups of 32 rows
    const int wn   = wid >> 2;         // 2 n-groups of 32 cols

    auto load_chunk = [&](int kc, int b){
        #pragma unroll
        for (int t = 0; t < 6; t++){
            int idx = tid + (t << 8);          // 0..1535 16B chunks
            const uint32_t* src;
            int rb, r;
            uint32_t roff;
            if (idx < 1024){
                src = g_lP; rb = i0; r = idx >> 3; roff = 0u;
            } else {
                int x = idx - 1024;
                src = g_rP; rb = j0; r = x >> 3; roff = 16384u;
            }
            int c = idx & 7;
            const void* gp = src + ((size_t)d*NDIM + rb + r)*NDIM + kc + (c << 2);
            uint32_t dst = sb + b*K2_BUF + roff + (r << 7) + (((c ^ (r & 7)) << 4));
            CP_ASYNC16(dst, gp);
        }
        CP_COMMIT();
    };

    float acc[2][4][4];
    #pragma unroll
    for (int a = 0; a < 2; a++)
        #pragma unroll
        for (int b = 0; b < 4; b++)
            #pragma unroll
            for (int q = 0; q < 4; q++) acc[a][b][q] = 0.f;

    load_chunk(0, 0);
    load_chunk(32, 1);

    #pragma unroll 1
    for (int t = 0; t < 16; t++){
        if (t == 15) asm volatile("cp.async.wait_group 0;" ::: "memory");
        else         asm volatile("cp.async.wait_group 1;" ::: "memory");
        __syncthreads();

        const uint32_t base = sb + (t & 1)*K2_BUF;
        #pragma unroll
        for (int fkk = 0; fkk < 4; fkk++){
            uint32_t ap[2][4], bp[4][2];
            #pragma unroll
            for (int mt = 0; mt < 2; mt++){
                int m = wm*32 + mt*16 + (lane & 15);
                int c = fkk*2 + (lane >> 4);
                ldsm4(ap[mt], base + (uint32_t)((m << 7) + (((c ^ (m & 7)) << 4))));
            }
            #pragma unroll
            for (int nt = 0; nt < 4; nt++){
                int l = lane & 15;
                int n = wn*32 + nt*8 + (l & 7);
                int c = fkk*2 + (l >> 3);
                ldsm2(bp[nt], base + 16384 + (uint32_t)((n << 7) + (((c ^ (n & 7)) << 4))));
            }
            #pragma unroll
            for (int mt = 0; mt < 2; mt++)
                #pragma unroll
                for (int nt = 0; nt < 4; nt++)
                    mma_f16(acc[mt][nt], ap[mt], bp[nt]);
        }
        __syncthreads();
        if (t + 2 < 16) load_chunk((t + 2)*32, t & 1);
    }

    #pragma unroll
    for (int mt = 0; mt < 2; mt++){
        int r0 = i0 + wm*32 + mt*16 + (lane >> 2);
        #pragma unroll
        for (int nt = 0; nt < 4; nt++){
            int c0 = j0 + wn*32 + nt*8 + (lane & 3)*2;
            float* p0 = &g_accT[((size_t)d*NDIM + r0)*NDIM + c0];
            float* p1 = &g_accT[((size_t)d*NDIM + r0 + 8)*NDIM + c0];
            p0[0] = acc[mt][nt][0]; p0[1] = acc[mt][nt][1];
            p1[0] = acc[mt][nt][2]; p1[1] = acc[mt][nt][3];
        }
    }
}

// ================= Kernel 3: LN(accT) @ opw.T + opb, times gate (64-j tiles, 2 CTA/SM) ====
// smem: A packed [0,32K) ; W packed [32K,96K) (prefetched at t=0)
__global__ void __launch_bounds__(256, 2)
k3_tc(const float* __restrict__ onw, const float* __restrict__ onb,
      const float* __restrict__ opb, float* __restrict__ out)
{
    extern __shared__ char smraw[];
    char* smb = (char*)(((uintptr_t)smraw + 1023) & ~(uintptr_t)1023);
    const uint32_t sb = smem_u32(smb);
    __shared__ float pb_s[128];
    __shared__ float sred[4][64], qred[4][64];
    __shared__ float mean_s[64], inv_s[64];

    const int tid  = threadIdx.x;
    const int lane = tid & 31;
    const int wid  = tid >> 5;
    const int wm   = wid & 1;
    const int wn   = wid >> 1;
    const int i_idx = blockIdx.x >> 3;
    const int j0    = (blockIdx.x & 7) * 64;
    const int row0  = i_idx*NDIM + j0;

    // prefetch op weight — overlaps with LN below
    #pragma unroll
    for (int t = 0; t < 16; t++){
        int idx = tid + (t << 8);
        int d = idx >> 5;
        int c = idx & 31;
        uint32_t off = (uint32_t)(d*512 + (((c ^ (d & 7)) << 4)));
        CP_ASYNC16(sb + 32768 + off, (const char*)(g_wp + 5*16384) + (idx << 4));
    }
    CP_COMMIT();
    if (tid < 128) pb_s[tid] = opb[tid];

    // ---- LN over d per j, operands in registers ----
    const int jj = tid & 63, qq4 = tid >> 6;
    float v[32];
    {
        const float* gp = g_accT + (size_t)(qq4*32)*NN + row0 + jj;
        float s = 0.f, ss = 0.f;
        #pragma unroll
        for (int t = 0; t < 32; t++){
            float x = gp[(size_t)t*NN];
            v[t] = x;
            s += x; ss += x*x;
        }
        sred[qq4][jj] = s; qred[qq4][jj] = ss;
    }
    __syncthreads();
    if (tid < 64){
        int j = tid;
        float S  = sred[0][j] + sred[1][j] + sred[2][j] + sred[3][j];
        float SS = qred[0][j] + qred[1][j] + qred[2][j] + qred[3][j];
        float m  = S * (1.f/128.f);
        float vv = fmaxf(SS * (1.f/128.f) - m*m, 0.f);
        mean_s[j] = m;
        inv_s[j]  = rsqrtf(vv + 1e-5f);
    }
    __syncthreads();
    {
        float m = mean_s[jj], iv = inv_s[jj];
        #pragma unroll
        for (int cc = 0; cc < 8; cc++){
            int c = qq4*8 + cc;
            int e = qq4*32 + cc*4;
            uint4 pv;
            uint32_t* pp = (uint32_t*)&pv;
            #pragma unroll
            for (int t = 0; t < 4; t++){
                float y = (v[cc*4 + t] - m)*iv*onw[e + t] + onb[e + t];
                pp[t] = pk_split(y);
            }
            uint32_t off = (uint32_t)(jj*512 + (((c ^ (jj & 7)) << 4)));
            *(uint4*)(smb + off) = pv;
        }
    }
    CP_WAIT0();
    __syncthreads();

    float acc[2][4][4];
    #pragma unroll
    for (int a = 0; a < 2; a++)
        #pragma unroll
        for (int b = 0; b < 4; b++)
            #pragma unroll
            for (int q = 0; q < 4; q++) acc[a][b][q] = 0.f;

    #pragma unroll 1
    for (int fkk = 0; fkk < 16; fkk++){
        uint32_t ap[2][4];
        #pragma unroll
        for (int mt = 0; mt < 2; mt++){
            int r = wm*32 + mt*16 + (lane & 15);
            int c = fkk*2 + (lane >> 4);
            ldsm4(ap[mt], sb + (uint32_t)(r*512 + (((c ^ (r & 7)) << 4))));
        }
        uint32_t bp[4][2];
        #pragma unroll
        for (int nt = 0; nt < 4; nt++){
            int l = lane & 15;
            int n = wn*32 + nt*8 + (l & 7);
            int c = fkk*2 + (l >> 3);
            ldsm2(bp[nt], sb + 32768 + (uint32_t)(n*512 + (((c ^ (n & 7)) << 4))));
        }
        #pragma unroll
        for (int mt = 0; mt < 2; mt++)
            #pragma unroll
            for (int nt = 0; nt < 4; nt++)
                mma_f16(acc[mt][nt], ap[mt], bp[nt]);
    }

    // epilogue: (acc + opb) * gate, direct global loads/stores
    #pragma unroll
    for (int mt = 0; mt < 2; mt++)
        #pragma unroll
        for (int nt = 0; nt < 4; nt++)
            #pragma unroll
            for (int qq = 0; qq < 2; qq++){
                int j = wm*32 + mt*16 + (lane >> 2) + qq*8;
                int n = wn*32 + nt*8 + ((lane & 3) << 1);
                size_t base = (size_t)(row0 + j)*DDIM + n;
                float2 g2 = *(const float2*)&g_gate[base];
                float2 o;
                o.x = (acc[mt][nt][qq*2+0] + pb_s[n+0]) * g2.x;
                o.y = (acc[mt][nt][qq*2+1] + pb_s[n+1]) * g2.y;
                *(float2*)&out[base] = o;
            }
}

extern "C" void kernel_launch(void* const* d_in, const int* in_sizes, int n_in,
                              void* d_out, int out_size)
{
    const float* pair = (const float*)d_in[0];
    const float* mask = (const float*)d_in[1];
    const float* nw   = (const float*)d_in[2];
    const float* nb   = (const float*)d_in[3];
    const float* lpw  = (const float*)d_in[4];
    const float* lpb  = (const float*)d_in[5];
    const float* lgw  = (const float*)d_in[6];
    const float* lgb  = (const float*)d_in[7];
    const float* rpw  = (const float*)d_in[8];
    const float* rpb  = (const float*)d_in[9];
    const float* rgw  = (const float*)d_in[10];
    const float* rgb  = (const float*)d_in[11];
    const float* onw  = (const float*)d_in[12];
    const float* onb  = (const float*)d_in[13];
    const float* opw  = (const float*)d_in[14];
    const float* opb  = (const float*)d_in[15];
    const float* ogw  = (const float*)d_in[16];
    const float* ogb  = (const float*)d_in[17];
    float* out = (float*)d_out;

    const int smem1 = 98304 + 1024;
    const int smem2 = 2*K2_BUF + 256;
    const int smem3 = 98304 + 1024;
    cudaFuncSetAttribute(k1_tc,  cudaFuncAttributeMaxDynamicSharedMemorySize, smem1);
    cudaFuncSetAttribute(k2_mma, cudaFuncAttributeMaxDynamicSharedMemorySize, smem2);
    cudaFuncSetAttribute(k3_tc,  cudaFuncAttributeMaxDynamicSharedMemorySize, smem3);

    k0_prep<<<dim3(64, 6), 256>>>(lpw, lgw, rpw, rgw, ogw, opw);

    k1_tc<<<NN/64, 256, smem1>>>(pair, mask, nw, nb, lpb, lgb, rpb, rgb, ogb);

    dim3 g2(32, 128);   // x = i-tile(4) x j-tile(8): consecutive blocks share the A tile in L2
    k2_mma<<<g2, 256, smem2>>>();

    k3_tc<<<NN/64, 256, smem3>>>(onw, onb, opb, out);
}